// round 1
// baseline (speedup 1.0000x reference)
#include <cuda_runtime.h>
#include <math.h>

#define DIM    768
#define HEADS  6
#define HDIM   128
#define LEVELS 3
#define POINTS 4
#define HID    192
#define BATCH  4
#define NQ     4096
#define NV     21504          // 128*128 + 64*64 + 32*32
#define MQ     (BATCH*NQ)     // 16384
#define MV     (BATCH*NV)     // 86016

// ---------------- scratch (static device globals; no runtime allocs) -------
__device__ float g_q   [(size_t)MQ*DIM];
__device__ float g_fn  [(size_t)MV*DIM];
__device__ float g_v   [(size_t)MV*DIM];
__device__ float g_off [(size_t)MQ*HEADS*LEVELS*POINTS*2];   // 144 per row
__device__ float g_aw  [(size_t)MQ*HEADS*LEVELS*POINTS];     // 72 per row
__device__ float g_samp[(size_t)MQ*DIM];
__device__ float g_x   [(size_t)MQ*DIM];
__device__ float g_xln [(size_t)MQ*DIM];
__device__ float g_y   [(size_t)MQ*HID];
__device__ float g_yg  [(size_t)MQ*HID];

// ---------------- LayerNorm over last dim = 768 ----------------------------
__global__ __launch_bounds__(256)
void ln_kernel(const float* __restrict__ in, const float* __restrict__ g,
               const float* __restrict__ b, float* __restrict__ out)
{
    const int row = blockIdx.x;
    const float* x = in + (size_t)row * DIM;
    float s = 0.f, ss = 0.f;
    for (int i = threadIdx.x; i < DIM; i += 256) { float v = x[i]; s += v; ss += v * v; }
    #pragma unroll
    for (int o = 16; o > 0; o >>= 1) {
        s  += __shfl_down_sync(0xffffffffu, s,  o);
        ss += __shfl_down_sync(0xffffffffu, ss, o);
    }
    __shared__ float sh_s[8], sh_ss[8];
    int w = threadIdx.x >> 5, l = threadIdx.x & 31;
    if (l == 0) { sh_s[w] = s; sh_ss[w] = ss; }
    __syncthreads();
    if (threadIdx.x == 0) {
        float ts = 0.f, tss = 0.f;
        #pragma unroll
        for (int i = 0; i < 8; i++) { ts += sh_s[i]; tss += sh_ss[i]; }
        float m   = ts * (1.f / DIM);
        float var = tss * (1.f / DIM) - m * m;
        sh_s[0]  = m;
        sh_ss[0] = rsqrtf(var + 1e-6f);
    }
    __syncthreads();
    float m = sh_s[0], r = sh_ss[0];
    for (int i = threadIdx.x; i < DIM; i += 256)
        out[(size_t)row * DIM + i] = (x[i] - m) * r * g[i] + b[i];
}

// ---------------- generic SGEMM: C = A[MxK] @ B[KxN] + bias (+add1)(+add2) -
// requires: M % 128 == 0, K % 8 == 0, N % 4 == 0, pointers 16B aligned
__global__ __launch_bounds__(256)
void sgemm_kernel(const float* __restrict__ A, const float* __restrict__ Bm,
                  const float* __restrict__ bias,
                  const float* __restrict__ add1, const float* __restrict__ add2,
                  float* __restrict__ C, int M, int N, int K)
{
    __shared__ float As[8][128];
    __shared__ float Bs[8][128];
    const int tid = threadIdx.x;
    const int rowBase = blockIdx.y * 128;
    const int colBase = blockIdx.x * 128;
    const int tx = tid & 15, ty = tid >> 4;

    const int ar_ = tid >> 1;          // A tile row (0..127)
    const int ak_ = (tid & 1) * 4;     // A tile k  (0 or 4)
    const int bk_ = tid >> 5;          // B tile k  (0..7)
    const int bc_ = (tid & 31) * 4;    // B tile col (0..124)

    float acc[8][8];
    #pragma unroll
    for (int i = 0; i < 8; i++)
        #pragma unroll
        for (int j = 0; j < 8; j++) acc[i][j] = 0.f;

    for (int k0 = 0; k0 < K; k0 += 8) {
        float4 av = *reinterpret_cast<const float4*>(A + (size_t)(rowBase + ar_) * K + k0 + ak_);
        As[ak_ + 0][ar_] = av.x; As[ak_ + 1][ar_] = av.y;
        As[ak_ + 2][ar_] = av.z; As[ak_ + 3][ar_] = av.w;
        if (colBase + bc_ < N) {
            float4 bv = *reinterpret_cast<const float4*>(Bm + (size_t)(k0 + bk_) * N + colBase + bc_);
            Bs[bk_][bc_ + 0] = bv.x; Bs[bk_][bc_ + 1] = bv.y;
            Bs[bk_][bc_ + 2] = bv.z; Bs[bk_][bc_ + 3] = bv.w;
        } else {
            Bs[bk_][bc_ + 0] = 0.f; Bs[bk_][bc_ + 1] = 0.f;
            Bs[bk_][bc_ + 2] = 0.f; Bs[bk_][bc_ + 3] = 0.f;
        }
        __syncthreads();
        #pragma unroll
        for (int kk = 0; kk < 8; kk++) {
            float ar[8], br[8];
            #pragma unroll
            for (int i = 0; i < 8; i++) ar[i] = As[kk][ty * 8 + i];
            #pragma unroll
            for (int j = 0; j < 8; j++) br[j] = Bs[kk][tx * 8 + j];
            #pragma unroll
            for (int i = 0; i < 8; i++)
                #pragma unroll
                for (int j = 0; j < 8; j++)
                    acc[i][j] += ar[i] * br[j];
        }
        __syncthreads();
    }
    #pragma unroll
    for (int i = 0; i < 8; i++) {
        int row = rowBase + ty * 8 + i;
        #pragma unroll
        for (int j = 0; j < 8; j++) {
            int col = colBase + tx * 8 + j;
            if (col < N) {
                size_t idx = (size_t)row * N + col;
                float vv = acc[i][j] + bias[col];
                if (add1) vv += add1[idx];
                if (add2) vv += add2[idx];
                C[idx] = vv;
            }
        }
    }
}

// ---------------- deformable sampling ---------------------------------------
// block = one (b, q); 768 threads: h = tid/128, c = tid%128
__global__ __launch_bounds__(768)
void sample_kernel(const float* __restrict__ refp, const float* __restrict__ off,
                   const float* __restrict__ aw, const float* __restrict__ v,
                   float* __restrict__ out)
{
    const int bq = blockIdx.x;
    const int b  = bq / NQ;
    const int tid = threadIdx.x;
    __shared__ float s_off[144], s_w[72], s_x[72], s_y[72], s_ref[6];
    if (tid < 144) s_off[tid] = off[(size_t)bq * 144 + tid];
    if (tid < 72)  s_w[tid]   = aw[(size_t)bq * 72 + tid];
    if (tid < 6)   s_ref[tid] = refp[(size_t)bq * 6 + tid];
    __syncthreads();

    const int Hl[3] = {128, 64, 32};
    const int Wl[3] = {128, 64, 32};
    const int st[3] = {0, 16384, 20480};

    if (tid < 6) {  // softmax per head over 12 (level,point) pairs
        int h = tid;
        float mx = -1e30f;
        for (int i = 0; i < 12; i++) mx = fmaxf(mx, s_w[h * 12 + i]);
        float sum = 0.f;
        for (int i = 0; i < 12; i++) { float e = expf(s_w[h * 12 + i] - mx); s_w[h * 12 + i] = e; sum += e; }
        float inv = 1.f / sum;
        for (int i = 0; i < 12; i++) s_w[h * 12 + i] *= inv;
    }
    if (tid < 72) {  // sampling pixel coordinates
        int h = tid / 12, lp = tid % 12, l = lp >> 2, p = lp & 3;
        float ox = s_off[h * 24 + l * 8 + p * 2 + 0];
        float oy = s_off[h * 24 + l * 8 + p * 2 + 1];
        float lx = s_ref[l * 2 + 0] + ox / (float)Wl[l];
        float ly = s_ref[l * 2 + 1] + oy / (float)Hl[l];
        s_x[tid] = lx * (float)Wl[l] - 0.5f;
        s_y[tid] = ly * (float)Hl[l] - 0.5f;
    }
    __syncthreads();

    const int h = tid >> 7;
    const int c = tid & 127;
    float acc = 0.f;
    #pragma unroll
    for (int lp = 0; lp < 12; lp++) {
        const int l  = lp >> 2;
        const int W_ = Wl[l], H_ = Hl[l];
        float w  = s_w[h * 12 + lp];
        float x  = s_x[h * 12 + lp];
        float y  = s_y[h * 12 + lp];
        float x0f = floorf(x), y0f = floorf(y);
        float wx = x - x0f, wy = y - y0f;
        int x0 = (int)x0f, y0 = (int)y0f;
        const float* base = v + ((size_t)b * NV + st[l]) * DIM + h * HDIM + c;
        float pv = 0.f;
        if (x0 >= 0 && x0 < W_ && y0 >= 0 && y0 < H_)
            pv += (1.f - wx) * (1.f - wy) * base[(size_t)(y0 * W_ + x0) * DIM];
        if (x0 + 1 >= 0 && x0 + 1 < W_ && y0 >= 0 && y0 < H_)
            pv += wx * (1.f - wy) * base[(size_t)(y0 * W_ + x0 + 1) * DIM];
        if (x0 >= 0 && x0 < W_ && y0 + 1 >= 0 && y0 + 1 < H_)
            pv += (1.f - wx) * wy * base[(size_t)((y0 + 1) * W_ + x0) * DIM];
        if (x0 + 1 >= 0 && x0 + 1 < W_ && y0 + 1 >= 0 && y0 + 1 < H_)
            pv += wx * wy * base[(size_t)((y0 + 1) * W_ + x0 + 1) * DIM];
        acc += w * pv;
    }
    out[(size_t)bq * DIM + h * HDIM + c] = acc;
}

// ---------------- depthwise 3x3 SAME + exact GELU ---------------------------
__global__ __launch_bounds__(HID)
void dwconv_gelu_kernel(const float* __restrict__ y, const float* __restrict__ w,
                        const float* __restrict__ bias, float* __restrict__ out)
{
    const int bhw = blockIdx.x;            // 0 .. B*64*64
    const int c   = threadIdx.x;           // 0 .. 191
    const int b   = bhw >> 12;
    const int hw  = bhw & 4095;
    const int h   = hw >> 6, ww = hw & 63;
    float acc = bias[c];
    #pragma unroll
    for (int ky = 0; ky < 3; ky++) {
        int hh = h + ky - 1;
        if (hh < 0 || hh >= 64) continue;
        #pragma unroll
        for (int kx = 0; kx < 3; kx++) {
            int xx = ww + kx - 1;
            if (xx < 0 || xx >= 64) continue;
            acc += y[((size_t)(b * 4096 + hh * 64 + xx)) * HID + c] * w[(ky * 3 + kx) * HID + c];
        }
    }
    out[(size_t)bhw * HID + c] = 0.5f * acc * (1.f + erff(acc * 0.70710678118654752f));
}

// ---------------- host orchestration ----------------------------------------
extern "C" void kernel_launch(void* const* d_in, const int* in_sizes, int n_in,
                              void* d_out, int out_size)
{
    const float* query = (const float*)d_in[0];
    const float* refp  = (const float*)d_in[1];
    const float* feat  = (const float*)d_in[2];
    // spatial_shapes/level_start_index/H/W are compile-time constants here.
    const int wb = n_in - 20;  // robust to whether H/W scalars are materialized
    const float* qn_g  = (const float*)d_in[wb + 0];
    const float* qn_b  = (const float*)d_in[wb + 1];
    const float* fn_g  = (const float*)d_in[wb + 2];
    const float* fn_b  = (const float*)d_in[wb + 3];
    const float* off_w = (const float*)d_in[wb + 4];
    const float* off_b = (const float*)d_in[wb + 5];
    const float* aw_w  = (const float*)d_in[wb + 6];
    const float* aw_b  = (const float*)d_in[wb + 7];
    const float* vp_w  = (const float*)d_in[wb + 8];
    const float* vp_b  = (const float*)d_in[wb + 9];
    const float* op_w  = (const float*)d_in[wb + 10];
    const float* op_b  = (const float*)d_in[wb + 11];
    const float* ffn_g = (const float*)d_in[wb + 12];
    const float* ffn_b = (const float*)d_in[wb + 13];
    const float* fc1_w = (const float*)d_in[wb + 14];
    const float* fc1_b = (const float*)d_in[wb + 15];
    const float* dw_w  = (const float*)d_in[wb + 16];
    const float* dw_b  = (const float*)d_in[wb + 17];
    const float* fc2_w = (const float*)d_in[wb + 18];
    const float* fc2_b = (const float*)d_in[wb + 19];

    float *q, *fn, *v, *off, *aw, *samp, *x, *xln, *y, *yg;
    cudaGetSymbolAddress((void**)&q,    g_q);
    cudaGetSymbolAddress((void**)&fn,   g_fn);
    cudaGetSymbolAddress((void**)&v,    g_v);
    cudaGetSymbolAddress((void**)&off,  g_off);
    cudaGetSymbolAddress((void**)&aw,   g_aw);
    cudaGetSymbolAddress((void**)&samp, g_samp);
    cudaGetSymbolAddress((void**)&x,    g_x);
    cudaGetSymbolAddress((void**)&xln,  g_xln);
    cudaGetSymbolAddress((void**)&y,    g_y);
    cudaGetSymbolAddress((void**)&yg,   g_yg);

    // 1) LayerNorms
    ln_kernel<<<MQ, 256>>>(query, qn_g, qn_b, q);
    ln_kernel<<<MV, 256>>>(feat,  fn_g, fn_b, fn);
    // 2) value projection (dominant GEMM)
    sgemm_kernel<<<dim3(6, MV / 128), 256>>>(fn, vp_w, vp_b, nullptr, nullptr, v, MV, DIM, DIM);
    // 3) offsets + attention weights
    sgemm_kernel<<<dim3(2, MQ / 128), 256>>>(q, off_w, off_b, nullptr, nullptr, off, MQ, 144, DIM);
    sgemm_kernel<<<dim3(1, MQ / 128), 256>>>(q, aw_w,  aw_b,  nullptr, nullptr, aw,  MQ, 72,  DIM);
    // 4) deformable bilinear sampling + weighted sum
    sample_kernel<<<MQ, 768>>>(refp, off, aw, v, samp);
    // 5) output projection + residuals: x = query + (samp@op_w + op_b + q)
    sgemm_kernel<<<dim3(6, MQ / 128), 256>>>(samp, op_w, op_b, q, query, x, MQ, DIM, DIM);
    // 6) FFN
    ln_kernel<<<MQ, 256>>>(x, ffn_g, ffn_b, xln);
    sgemm_kernel<<<dim3(2, MQ / 128), 256>>>(xln, fc1_w, fc1_b, nullptr, nullptr, y, MQ, HID, DIM);
    dwconv_gelu_kernel<<<MQ, HID>>>(y, dw_w, dw_b, yg);
    // 7) fc2 + final residual directly into d_out
    sgemm_kernel<<<dim3(6, MQ / 128), 256>>>(yg, fc2_w, fc2_b, x, nullptr, (float*)d_out, MQ, DIM, HID);
}

// round 3
// speedup vs baseline: 1.5962x; 1.5962x over previous
#include <cuda_runtime.h>
#include <cuda_bf16.h>
#include <math.h>
#include <stdint.h>

#define DIM    768
#define HEADS  6
#define HDIM   128
#define HID    192
#define BATCH  4
#define NQ     4096
#define NV     21504
#define MQ     (BATCH*NQ)     // 16384
#define MV     (BATCH*NV)     // 86016
#define KC     64             // K elements per chunk (128 bytes bf16)

// ---------------- helpers ----------------------------------------------------
__device__ __forceinline__ uint32_t smem_u32(const void* p) {
    uint32_t a;
    asm("{ .reg .u64 t; cvta.to.shared.u64 t, %1; cvt.u32.u64 %0, t; }" : "=r"(a) : "l"(p));
    return a;
}
__device__ __forceinline__ void cp16(uint32_t s, const void* g) {
    asm volatile("cp.async.cg.shared.global [%0], [%1], 16;" :: "r"(s), "l"(g));
}
__device__ __forceinline__ void cp_commit() { asm volatile("cp.async.commit_group;"); }
__device__ __forceinline__ void cp_wait0()  { asm volatile("cp.async.wait_group 0;"); }

__device__ __forceinline__ void ldm4(uint32_t* r, uint32_t a) {
    asm volatile("ldmatrix.sync.aligned.m8n8.x4.shared.b16 {%0,%1,%2,%3}, [%4];"
        : "=r"(r[0]), "=r"(r[1]), "=r"(r[2]), "=r"(r[3]) : "r"(a));
}
__device__ __forceinline__ void mma16816(float* c, const uint32_t* a, const uint32_t* b) {
    asm volatile("mma.sync.aligned.m16n8k16.row.col.f32.bf16.bf16.f32 "
        "{%0,%1,%2,%3}, {%4,%5,%6,%7}, {%8,%9}, {%0,%1,%2,%3};"
        : "+f"(c[0]), "+f"(c[1]), "+f"(c[2]), "+f"(c[3])
        : "r"(a[0]), "r"(a[1]), "r"(a[2]), "r"(a[3]), "r"(b[0]), "r"(b[1]));
}

// ---------------- scratch ----------------------------------------------------
__device__ __align__(16) float         g_qf  [(size_t)MQ*DIM];
__device__ __align__(16) __nv_bfloat16 g_qh  [(size_t)MQ*DIM];
__device__ __align__(16) __nv_bfloat16 g_ql  [(size_t)MQ*DIM];
__device__ __align__(16) __nv_bfloat16 g_fnh [(size_t)MV*DIM];
__device__ __align__(16) __nv_bfloat16 g_fnl [(size_t)MV*DIM];
__device__ __align__(16) float         g_v   [(size_t)MV*DIM];
__device__ __align__(16) float         g_off [(size_t)MQ*144];
__device__ __align__(16) float         g_aw  [(size_t)MQ*72];
__device__ __align__(16) __nv_bfloat16 g_sph [(size_t)MQ*DIM];
__device__ __align__(16) __nv_bfloat16 g_spl [(size_t)MQ*DIM];
__device__ __align__(16) float         g_x   [(size_t)MQ*DIM];
__device__ __align__(16) __nv_bfloat16 g_xlh [(size_t)MQ*DIM];
__device__ __align__(16) __nv_bfloat16 g_xll [(size_t)MQ*DIM];
__device__ __align__(16) float         g_y   [(size_t)MQ*HID];
__device__ __align__(16) __nv_bfloat16 g_ygh [(size_t)MQ*HID];
__device__ __align__(16) __nv_bfloat16 g_ygl [(size_t)MQ*HID];
// pre-transposed, split weights [Npad, K]
__device__ __align__(16) __nv_bfloat16 g_wvh[768*768],  g_wvl[768*768];
__device__ __align__(16) __nv_bfloat16 g_woh[768*768],  g_wol[768*768];
__device__ __align__(16) __nv_bfloat16 g_wfh[256*768],  g_wfl[256*768];   // off: N=144 -> 256
__device__ __align__(16) __nv_bfloat16 g_wah[128*768],  g_wal[128*768];   // aw:  N=72  -> 128
__device__ __align__(16) __nv_bfloat16 g_w1h[256*768],  g_w1l[256*768];   // fc1: N=192 -> 256
__device__ __align__(16) __nv_bfloat16 g_w2h[768*192],  g_w2l[768*192];   // fc2

// ---------------- weight transpose + split: W[K,N] -> T[Npad,K] bf16 hi/lo ---
__global__ __launch_bounds__(256)
void wprep_kernel(const float* __restrict__ W, __nv_bfloat16* __restrict__ Th,
                  __nv_bfloat16* __restrict__ Tl, int N, int Npad, int K)
{
    int idx = blockIdx.x * 256 + threadIdx.x;
    if (idx >= Npad * K) return;
    int n = idx / K, k = idx - n * K;
    float v = (n < N) ? W[(size_t)k * N + n] : 0.f;
    __nv_bfloat16 h = __float2bfloat16(v);
    Th[idx] = h;
    Tl[idx] = __float2bfloat16(v - __bfloat162float(h));
}

// ---------------- LayerNorm (768) -> optional fp32 + bf16 hi/lo --------------
__global__ __launch_bounds__(256)
void ln_kernel(const float* __restrict__ in, const float* __restrict__ g,
               const float* __restrict__ b, float* __restrict__ outf,
               __nv_bfloat16* __restrict__ outh, __nv_bfloat16* __restrict__ outl)
{
    const int row = blockIdx.x;
    const float* x = in + (size_t)row * DIM;
    float s = 0.f, ss = 0.f;
    for (int i = threadIdx.x; i < DIM; i += 256) { float v = x[i]; s += v; ss += v * v; }
    #pragma unroll
    for (int o = 16; o > 0; o >>= 1) {
        s  += __shfl_down_sync(0xffffffffu, s,  o);
        ss += __shfl_down_sync(0xffffffffu, ss, o);
    }
    __shared__ float sh_s[8], sh_ss[8];
    int w = threadIdx.x >> 5, l = threadIdx.x & 31;
    if (l == 0) { sh_s[w] = s; sh_ss[w] = ss; }
    __syncthreads();
    if (threadIdx.x == 0) {
        float ts = 0.f, tss = 0.f;
        #pragma unroll
        for (int i = 0; i < 8; i++) { ts += sh_s[i]; tss += sh_ss[i]; }
        float m   = ts * (1.f / DIM);
        float var = tss * (1.f / DIM) - m * m;
        sh_s[0]  = m;
        sh_ss[0] = rsqrtf(var + 1e-6f);
    }
    __syncthreads();
    float m = sh_s[0], r = sh_ss[0];
    for (int i = threadIdx.x; i < DIM; i += 256) {
        float v = (x[i] - m) * r * g[i] + b[i];
        size_t idx = (size_t)row * DIM + i;
        if (outf) outf[idx] = v;
        __nv_bfloat16 h = __float2bfloat16(v);
        outh[idx] = h;
        outl[idx] = __float2bfloat16(v - __bfloat162float(h));
    }
}

// ---------------- split-bf16 mma.sync GEMM -----------------------------------
// C[M,N] = A[M,K] @ B_t[N,K]^T + bias (+add1)(+add2), fp32 out.
// Ah/Al bf16 [M,K] row-major; Bh/Bl bf16 [Npad,K] row-major.
// CTA tile 128x128, 8 warps (4m x 2n), warp tile 32x64.
// Double-buffered cp.async, K-chunk 64. 3 MMAs per tile per k16 (split).
__global__ __launch_bounds__(256, 1)
void mma_gemm(const __nv_bfloat16* __restrict__ Ah, const __nv_bfloat16* __restrict__ Al,
              const __nv_bfloat16* __restrict__ Bh, const __nv_bfloat16* __restrict__ Bl,
              const float* __restrict__ bias, const float* __restrict__ add1,
              const float* __restrict__ add2, float* __restrict__ C,
              int M, int N, int K)
{
    extern __shared__ char smraw[];
    char* sm = (char*)(((uintptr_t)smraw + 1023) & ~(uintptr_t)1023);
    const uint32_t smBase = smem_u32(sm);

    const int tid  = threadIdx.x;
    const int lane = tid & 31, wid = tid >> 5;
    const int wm = (wid & 3) * 32;      // warp m offset in tile
    const int wn = (wid >> 2) * 64;     // warp n offset in tile
    const int m0 = blockIdx.y * 128, n0 = blockIdx.x * 128;

    const size_t strA = (size_t)K * 2;
    const char* gAh = (const char*)Ah + (size_t)m0 * strA;
    const char* gAl = (const char*)Al + (size_t)m0 * strA;
    const char* gBh = (const char*)Bh + (size_t)n0 * strA;
    const char* gBl = (const char*)Bl + (size_t)n0 * strA;

    // ldmatrix per-lane logical coords
    const int aRow = lane & 15;                 // + (lane>=16 ? col+16)
    const int aCol = (lane >> 4) * 16;
    const int bRowOff = ((lane & 16) >> 1) + (lane & 7);
    const int bCol = (lane & 8) * 2;

    uint32_t aBase[2], aXor[2];
    #pragma unroll
    for (int mt = 0; mt < 2; mt++) {
        int row = wm + mt * 16 + aRow;
        aBase[mt] = (uint32_t)(row * 128);
        aXor[mt]  = (uint32_t)(aCol ^ ((row & 7) * 16));
    }
    uint32_t bBase[4], bXor[4];
    #pragma unroll
    for (int np = 0; np < 4; np++) {
        int row = wn + np * 16 + bRowOff;
        bBase[np] = (uint32_t)(32768 + row * 128);
        bXor[np]  = (uint32_t)(bCol ^ ((row & 7) * 16));
    }

    float acc[2][8][4];
    #pragma unroll
    for (int i = 0; i < 2; i++)
        #pragma unroll
        for (int j = 0; j < 8; j++)
            #pragma unroll
            for (int k = 0; k < 4; k++) acc[i][j][k] = 0.f;

    const int nCh = K >> 6;

    // chunk loader: 4 tiles x 1024 16B units, 16 cp.async per thread
    #define LOAD_CHUNK(kc_, st_) do {                                           \
        uint32_t dst = smBase + (uint32_t)(st_) * 65536u;                       \
        size_t kb_ = (size_t)(kc_) * 128;                                       \
        _Pragma("unroll")                                                       \
        for (int i_ = 0; i_ < 4; i_++) {                                        \
            int u_ = tid + 256 * i_;                                            \
            int r_ = u_ >> 3, c_ = u_ & 7;                                      \
            uint32_t off_ = (uint32_t)(r_ * 128 + c_ * 16);                     \
            uint32_t sw_ = off_ ^ ((off_ >> 3) & 0x70);                         \
            size_t go_ = (size_t)r_ * strA + kb_ + (size_t)c_ * 16;             \
            cp16(dst + sw_,          gAh + go_);                                \
            cp16(dst + 16384 + sw_,  gAl + go_);                                \
            cp16(dst + 32768 + sw_,  gBh + go_);                                \
            cp16(dst + 49152 + sw_,  gBl + go_);                                \
        }                                                                       \
    } while (0)

    LOAD_CHUNK(0, 0);
    cp_commit();

    for (int kc = 0; kc < nCh; kc++) {
        const int st = kc & 1;
        cp_wait0();
        __syncthreads();
        if (kc + 1 < nCh) { LOAD_CHUNK(kc + 1, st ^ 1); cp_commit(); }

        const uint32_t stBase = smBase + (uint32_t)st * 65536u;
        #pragma unroll
        for (int ks = 0; ks < 4; ks++) {
            const uint32_t kb = (uint32_t)(ks * 32);
            uint32_t ah[2][4], al[2][4], bh[8][2], bl[8][2];
            #pragma unroll
            for (int mt = 0; mt < 2; mt++) {
                uint32_t ad = stBase + aBase[mt] + (kb ^ aXor[mt]);
                ldm4(ah[mt], ad);
                ldm4(al[mt], ad + 16384);
            }
            #pragma unroll
            for (int np = 0; np < 4; np++) {
                uint32_t ad = stBase + bBase[np] + (kb ^ bXor[np]);
                ldm4(&bh[2 * np][0], ad);
                ldm4(&bl[2 * np][0], ad + 16384);
            }
            #pragma unroll
            for (int mt = 0; mt < 2; mt++)
                #pragma unroll
                for (int nt = 0; nt < 8; nt++) mma16816(acc[mt][nt], ah[mt], bh[nt]);
            #pragma unroll
            for (int mt = 0; mt < 2; mt++)
                #pragma unroll
                for (int nt = 0; nt < 8; nt++) mma16816(acc[mt][nt], ah[mt], bl[nt]);
            #pragma unroll
            for (int mt = 0; mt < 2; mt++)
                #pragma unroll
                for (int nt = 0; nt < 8; nt++) mma16816(acc[mt][nt], al[mt], bh[nt]);
        }
    }
    #undef LOAD_CHUNK

    // epilogue from register accumulators
    #pragma unroll
    for (int mt = 0; mt < 2; mt++) {
        #pragma unroll
        for (int nt = 0; nt < 8; nt++) {
            int row = m0 + wm + mt * 16 + (lane >> 2);
            int col = n0 + wn + nt * 8 + 2 * (lane & 3);
            if (col < N) {
                size_t i0 = (size_t)row * N + col;
                float v0 = acc[mt][nt][0] + bias[col];
                float v1 = acc[mt][nt][1] + bias[col + 1];
                if (add1) { v0 += add1[i0]; v1 += add1[i0 + 1]; }
                if (add2) { v0 += add2[i0]; v1 += add2[i0 + 1]; }
                C[i0] = v0; C[i0 + 1] = v1;
                size_t i1 = (size_t)(row + 8) * N + col;
                float v2 = acc[mt][nt][2] + bias[col];
                float v3 = acc[mt][nt][3] + bias[col + 1];
                if (add1) { v2 += add1[i1]; v3 += add1[i1 + 1]; }
                if (add2) { v2 += add2[i1]; v3 += add2[i1 + 1]; }
                C[i1] = v2; C[i1 + 1] = v3;
            }
        }
    }
}

// ---------------- deformable sampling -> bf16 hi/lo --------------------------
__global__ __launch_bounds__(768)
void sample_kernel(const float* __restrict__ refp, const float* __restrict__ off,
                   const float* __restrict__ aw, const float* __restrict__ v,
                   __nv_bfloat16* __restrict__ outh, __nv_bfloat16* __restrict__ outl)
{
    const int bq = blockIdx.x;
    const int b  = bq / NQ;
    const int tid = threadIdx.x;
    __shared__ float s_off[144], s_w[72], s_x[72], s_y[72], s_ref[6];
    if (tid < 144) s_off[tid] = off[(size_t)bq * 144 + tid];
    if (tid < 72)  s_w[tid]   = aw[(size_t)bq * 72 + tid];
    if (tid < 6)   s_ref[tid] = refp[(size_t)bq * 6 + tid];
    __syncthreads();

    const int Hl[3] = {128, 64, 32};
    const int Wl[3] = {128, 64, 32};
    const int st[3] = {0, 16384, 20480};

    if (tid < 6) {
        int h = tid;
        float mx = -1e30f;
        for (int i = 0; i < 12; i++) mx = fmaxf(mx, s_w[h * 12 + i]);
        float sum = 0.f;
        for (int i = 0; i < 12; i++) { float e = expf(s_w[h * 12 + i] - mx); s_w[h * 12 + i] = e; sum += e; }
        float inv = 1.f / sum;
        for (int i = 0; i < 12; i++) s_w[h * 12 + i] *= inv;
    }
    if (tid < 72) {
        int h = tid / 12, lp = tid % 12, l = lp >> 2, p = lp & 3;
        float ox = s_off[h * 24 + l * 8 + p * 2 + 0];
        float oy = s_off[h * 24 + l * 8 + p * 2 + 1];
        float lx = s_ref[l * 2 + 0] + ox / (float)Wl[l];
        float ly = s_ref[l * 2 + 1] + oy / (float)Hl[l];
        s_x[tid] = lx * (float)Wl[l] - 0.5f;
        s_y[tid] = ly * (float)Hl[l] - 0.5f;
    }
    __syncthreads();

    const int h = tid >> 7;
    const int c = tid & 127;
    float acc = 0.f;
    #pragma unroll
    for (int lp = 0; lp < 12; lp++) {
        const int l  = lp >> 2;
        const int W_ = Wl[l], H_ = Hl[l];
        float w  = s_w[h * 12 + lp];
        float x  = s_x[h * 12 + lp];
        float y  = s_y[h * 12 + lp];
        float x0f = floorf(x), y0f = floorf(y);
        float wx = x - x0f, wy = y - y0f;
        int x0 = (int)x0f, y0 = (int)y0f;
        const float* base = v + ((size_t)b * NV + st[l]) * DIM + h * HDIM + c;
        float pv = 0.f;
        if (x0 >= 0 && x0 < W_ && y0 >= 0 && y0 < H_)
            pv += (1.f - wx) * (1.f - wy) * base[(size_t)(y0 * W_ + x0) * DIM];
        if (x0 + 1 >= 0 && x0 + 1 < W_ && y0 >= 0 && y0 < H_)
            pv += wx * (1.f - wy) * base[(size_t)(y0 * W_ + x0 + 1) * DIM];
        if (x0 >= 0 && x0 < W_ && y0 + 1 >= 0 && y0 + 1 < H_)
            pv += (1.f - wx) * wy * base[(size_t)((y0 + 1) * W_ + x0) * DIM];
        if (x0 + 1 >= 0 && x0 + 1 < W_ && y0 + 1 >= 0 && y0 + 1 < H_)
            pv += wx * wy * base[(size_t)((y0 + 1) * W_ + x0 + 1) * DIM];
        acc += w * pv;
    }
    size_t idx = (size_t)bq * DIM + h * HDIM + c;
    __nv_bfloat16 hh = __float2bfloat16(acc);
    outh[idx] = hh;
    outl[idx] = __float2bfloat16(acc - __bfloat162float(hh));
}

// ---------------- depthwise 3x3 + GELU -> bf16 hi/lo -------------------------
__global__ __launch_bounds__(HID)
void dwconv_gelu_kernel(const float* __restrict__ y, const float* __restrict__ w,
                        const float* __restrict__ bias,
                        __nv_bfloat16* __restrict__ outh, __nv_bfloat16* __restrict__ outl)
{
    const int bhw = blockIdx.x;
    const int c   = threadIdx.x;
    const int b   = bhw >> 12;
    const int hw  = bhw & 4095;
    const int h   = hw >> 6, ww = hw & 63;
    float acc = bias[c];
    #pragma unroll
    for (int ky = 0; ky < 3; ky++) {
        int hh = h + ky - 1;
        if (hh < 0 || hh >= 64) continue;
        #pragma unroll
        for (int kx = 0; kx < 3; kx++) {
            int xx = ww + kx - 1;
            if (xx < 0 || xx >= 64) continue;
            acc += y[((size_t)(b * 4096 + hh * 64 + xx)) * HID + c] * w[(ky * 3 + kx) * HID + c];
        }
    }
    float g = 0.5f * acc * (1.f + erff(acc * 0.70710678118654752f));
    size_t idx = (size_t)bhw * HID + c;
    __nv_bfloat16 hv = __float2bfloat16(g);
    outh[idx] = hv;
    outl[idx] = __float2bfloat16(g - __bfloat162float(hv));
}

// ---------------- host orchestration ----------------------------------------
#define GEMM_SMEM (131072 + 1024)

extern "C" void kernel_launch(void* const* d_in, const int* in_sizes, int n_in,
                              void* d_out, int out_size)
{
    const float* query = (const float*)d_in[0];
    const float* refp  = (const float*)d_in[1];
    const float* feat  = (const float*)d_in[2];
    const int wb = n_in - 20;
    const float* qn_g  = (const float*)d_in[wb + 0];
    const float* qn_b  = (const float*)d_in[wb + 1];
    const float* fn_g  = (const float*)d_in[wb + 2];
    const float* fn_b  = (const float*)d_in[wb + 3];
    const float* off_w = (const float*)d_in[wb + 4];
    const float* off_b = (const float*)d_in[wb + 5];
    const float* aw_w  = (const float*)d_in[wb + 6];
    const float* aw_b  = (const float*)d_in[wb + 7];
    const float* vp_w  = (const float*)d_in[wb + 8];
    const float* vp_b  = (const float*)d_in[wb + 9];
    const float* op_w  = (const float*)d_in[wb + 10];
    const float* op_b  = (const float*)d_in[wb + 11];
    const float* ffn_g = (const float*)d_in[wb + 12];
    const float* ffn_b = (const float*)d_in[wb + 13];
    const float* fc1_w = (const float*)d_in[wb + 14];
    const float* fc1_b = (const float*)d_in[wb + 15];
    const float* dw_w  = (const float*)d_in[wb + 16];
    const float* dw_b  = (const float*)d_in[wb + 17];
    const float* fc2_w = (const float*)d_in[wb + 18];
    const float* fc2_b = (const float*)d_in[wb + 19];

    static bool attr_done = false;
    if (!attr_done) {
        cudaFuncSetAttribute(mma_gemm, cudaFuncAttributeMaxDynamicSharedMemorySize, GEMM_SMEM);
        attr_done = true;
    }

    float *qf, *v, *off, *aw, *x, *y;
    __nv_bfloat16 *qh, *ql, *fnh, *fnl, *sph, *spl, *xlh, *xll, *ygh, *ygl;
    __nv_bfloat16 *wvh, *wvl, *woh, *wol, *wfh, *wfl, *wah, *wal, *w1h, *w1l, *w2h, *w2l;
    cudaGetSymbolAddress((void**)&qf,  g_qf);  cudaGetSymbolAddress((void**)&qh,  g_qh);
    cudaGetSymbolAddress((void**)&ql,  g_ql);  cudaGetSymbolAddress((void**)&fnh, g_fnh);
    cudaGetSymbolAddress((void**)&fnl, g_fnl); cudaGetSymbolAddress((void**)&v,   g_v);
    cudaGetSymbolAddress((void**)&off, g_off); cudaGetSymbolAddress((void**)&aw,  g_aw);
    cudaGetSymbolAddress((void**)&sph, g_sph); cudaGetSymbolAddress((void**)&spl, g_spl);
    cudaGetSymbolAddress((void**)&x,   g_x);   cudaGetSymbolAddress((void**)&xlh, g_xlh);
    cudaGetSymbolAddress((void**)&xll, g_xll); cudaGetSymbolAddress((void**)&y,   g_y);
    cudaGetSymbolAddress((void**)&ygh, g_ygh); cudaGetSymbolAddress((void**)&ygl, g_ygl);
    cudaGetSymbolAddress((void**)&wvh, g_wvh); cudaGetSymbolAddress((void**)&wvl, g_wvl);
    cudaGetSymbolAddress((void**)&woh, g_woh); cudaGetSymbolAddress((void**)&wol, g_wol);
    cudaGetSymbolAddress((void**)&wfh, g_wfh); cudaGetSymbolAddress((void**)&wfl, g_wfl);
    cudaGetSymbolAddress((void**)&wah, g_wah); cudaGetSymbolAddress((void**)&wal, g_wal);
    cudaGetSymbolAddress((void**)&w1h, g_w1h); cudaGetSymbolAddress((void**)&w1l, g_w1l);
    cudaGetSymbolAddress((void**)&w2h, g_w2h); cudaGetSymbolAddress((void**)&w2l, g_w2l);

    // weight prep (transpose + split)
    wprep_kernel<<<(768*768 + 255)/256, 256>>>(vp_w,  wvh, wvl, 768, 768, 768);
    wprep_kernel<<<(768*768 + 255)/256, 256>>>(op_w,  woh, wol, 768, 768, 768);
    wprep_kernel<<<(256*768 + 255)/256, 256>>>(off_w, wfh, wfl, 144, 256, 768);
    wprep_kernel<<<(128*768 + 255)/256, 256>>>(aw_w,  wah, wal, 72,  128, 768);
    wprep_kernel<<<(256*768 + 255)/256, 256>>>(fc1_w, w1h, w1l, 192, 256, 768);
    wprep_kernel<<<(768*192 + 255)/256, 256>>>(fc2_w, w2h, w2l, 768, 768, 192);

    // LayerNorms (with bf16 split outputs)
    ln_kernel<<<MQ, 256>>>(query, qn_g, qn_b, qf, qh, ql);
    ln_kernel<<<MV, 256>>>(feat,  fn_g, fn_b, nullptr, fnh, fnl);

    // value projection
    mma_gemm<<<dim3(6, MV/128), 256, GEMM_SMEM>>>(fnh, fnl, wvh, wvl, vp_b, nullptr, nullptr, v, MV, 768, 768);
    // offsets + attention weights
    mma_gemm<<<dim3(2, MQ/128), 256, GEMM_SMEM>>>(qh, ql, wfh, wfl, off_b, nullptr, nullptr, off, MQ, 144, 768);
    mma_gemm<<<dim3(1, MQ/128), 256, GEMM_SMEM>>>(qh, ql, wah, wal, aw_b,  nullptr, nullptr, aw,  MQ, 72,  768);
    // sampling
    sample_kernel<<<MQ, 768>>>(refp, off, aw, v, sph, spl);
    // output projection + residuals: x = query + q + samp@op_w + op_b
    mma_gemm<<<dim3(6, MQ/128), 256, GEMM_SMEM>>>(sph, spl, woh, wol, op_b, qf, query, x, MQ, 768, 768);
    // FFN
    ln_kernel<<<MQ, 256>>>(x, ffn_g, ffn_b, nullptr, xlh, xll);
    mma_gemm<<<dim3(2, MQ/128), 256, GEMM_SMEM>>>(xlh, xll, w1h, w1l, fc1_b, nullptr, nullptr, y, MQ, 192, 768);
    dwconv_gelu_kernel<<<MQ, HID>>>(y, dw_w, dw_b, ygh, ygl);
    // fc2 + final residual into d_out
    mma_gemm<<<dim3(6, MQ/128), 256, GEMM_SMEM>>>(ygh, ygl, w2h, w2l, fc2_b, x, nullptr, (float*)d_out, MQ, 768, 192);
}

// round 4
// speedup vs baseline: 3.3527x; 2.1005x over previous
#include <cuda_runtime.h>
#include <cuda_bf16.h>
#include <math.h>
#include <stdint.h>

#define DIM    768
#define HEADS  6
#define HDIM   128
#define HID    192
#define BATCH  4
#define NQ     4096
#define NV     21504
#define MQ     (BATCH*NQ)     // 16384
#define MV     (BATCH*NV)     // 86016

// ---------------- helpers ----------------------------------------------------
__device__ __forceinline__ uint32_t smem_u32(const void* p) {
    uint32_t a;
    asm("{ .reg .u64 t; cvta.to.shared.u64 t, %1; cvt.u32.u64 %0, t; }" : "=r"(a) : "l"(p));
    return a;
}
__device__ __forceinline__ void cp16(uint32_t s, const void* g) {
    asm volatile("cp.async.cg.shared.global [%0], [%1], 16;" :: "r"(s), "l"(g));
}
__device__ __forceinline__ void cp_commit() { asm volatile("cp.async.commit_group;"); }
__device__ __forceinline__ void cp_wait0()  { asm volatile("cp.async.wait_group 0;"); }

__device__ __forceinline__ void ldm4(uint32_t* r, uint32_t a) {
    asm volatile("ldmatrix.sync.aligned.m8n8.x4.shared.b16 {%0,%1,%2,%3}, [%4];"
        : "=r"(r[0]), "=r"(r[1]), "=r"(r[2]), "=r"(r[3]) : "r"(a));
}
__device__ __forceinline__ void mma16816(float* c, const uint32_t* a, const uint32_t* b) {
    asm volatile("mma.sync.aligned.m16n8k16.row.col.f32.bf16.bf16.f32 "
        "{%0,%1,%2,%3}, {%4,%5,%6,%7}, {%8,%9}, {%0,%1,%2,%3};"
        : "+f"(c[0]), "+f"(c[1]), "+f"(c[2]), "+f"(c[3])
        : "r"(a[0]), "r"(a[1]), "r"(a[2]), "r"(a[3]), "r"(b[0]), "r"(b[1]));
}

// ---------------- scratch ----------------------------------------------------
__device__ __align__(16) float         g_qf  [(size_t)MQ*DIM];
__device__ __align__(16) __nv_bfloat16 g_qh  [(size_t)MQ*DIM];
__device__ __align__(16) __nv_bfloat16 g_fnh [(size_t)MV*DIM];
__device__ __align__(16) __nv_bfloat16 g_vb  [(size_t)MV*DIM];     // v as bf16
__device__ __align__(16) float         g_off [(size_t)MQ*144];
__device__ __align__(16) float         g_aw  [(size_t)MQ*72];
__device__ __align__(16) __nv_bfloat16 g_sph [(size_t)MQ*DIM];
__device__ __align__(16) float         g_x   [(size_t)MQ*DIM];
__device__ __align__(16) __nv_bfloat16 g_xlh [(size_t)MQ*DIM];
__device__ __align__(16) float         g_y   [(size_t)MQ*HID];
__device__ __align__(16) __nv_bfloat16 g_ygh [(size_t)MQ*HID];
// pre-transposed, split weights [Npad, K] (hi + lo)
__device__ __align__(16) __nv_bfloat16 g_wvh[768*768],  g_wvl[768*768];
__device__ __align__(16) __nv_bfloat16 g_woh[768*768],  g_wol[768*768];
__device__ __align__(16) __nv_bfloat16 g_wfh[256*768],  g_wfl[256*768];   // off N=144->256
__device__ __align__(16) __nv_bfloat16 g_wah[128*768],  g_wal[128*768];   // aw  N=72 ->128
__device__ __align__(16) __nv_bfloat16 g_w1h[256*768],  g_w1l[256*768];   // fc1 N=192->256
__device__ __align__(16) __nv_bfloat16 g_w2h[768*192],  g_w2l[768*192];   // fc2

// ---------------- weight transpose + split: W[K,N] -> T[Npad,K] bf16 hi/lo ---
__global__ __launch_bounds__(256)
void wprep_kernel(const float* __restrict__ W, __nv_bfloat16* __restrict__ Th,
                  __nv_bfloat16* __restrict__ Tl, int N, int Npad, int K)
{
    int idx = blockIdx.x * 256 + threadIdx.x;
    if (idx >= Npad * K) return;
    int n = idx / K, k = idx - n * K;
    float v = (n < N) ? W[(size_t)k * N + n] : 0.f;
    __nv_bfloat16 h = __float2bfloat16(v);
    Th[idx] = h;
    Tl[idx] = __float2bfloat16(v - __bfloat162float(h));
}

// ---------------- LayerNorm (768) -> optional fp32 + bf16 ------------------
__global__ __launch_bounds__(256)
void ln_kernel(const float* __restrict__ in, const float* __restrict__ g,
               const float* __restrict__ b, float* __restrict__ outf,
               __nv_bfloat16* __restrict__ outh)
{
    const int row = blockIdx.x;
    const float* x = in + (size_t)row * DIM;
    float s = 0.f, ss = 0.f;
    for (int i = threadIdx.x; i < DIM; i += 256) { float v = x[i]; s += v; ss += v * v; }
    #pragma unroll
    for (int o = 16; o > 0; o >>= 1) {
        s  += __shfl_down_sync(0xffffffffu, s,  o);
        ss += __shfl_down_sync(0xffffffffu, ss, o);
    }
    __shared__ float sh_s[8], sh_ss[8];
    int w = threadIdx.x >> 5, l = threadIdx.x & 31;
    if (l == 0) { sh_s[w] = s; sh_ss[w] = ss; }
    __syncthreads();
    if (threadIdx.x == 0) {
        float ts = 0.f, tss = 0.f;
        #pragma unroll
        for (int i = 0; i < 8; i++) { ts += sh_s[i]; tss += sh_ss[i]; }
        float m   = ts * (1.f / DIM);
        float var = tss * (1.f / DIM) - m * m;
        sh_s[0]  = m;
        sh_ss[0] = rsqrtf(var + 1e-6f);
    }
    __syncthreads();
    float m = sh_s[0], r = sh_ss[0];
    for (int i = threadIdx.x; i < DIM; i += 256) {
        float v = (x[i] - m) * r * g[i] + b[i];
        size_t idx = (size_t)row * DIM + i;
        if (outf) outf[idx] = v;
        outh[idx] = __float2bfloat16(v);
    }
}

// ---------------- 2-term split-bf16 mma.sync GEMM ----------------------------
// C = A[M,K] @ B_t[N,K]^T + bias (+add1)(+add2).  out fp32 (C) and/or bf16 (Cb).
// A bf16 [M,K]; Bh/Bl bf16 [Npad,K]. Per k16 tile: A*Bh + A*Bl.
// CTA tile 128x128, 8 warps (4m x 2n). Double-buffered cp.async, chunk K=64.
__global__ __launch_bounds__(256, 2)
void mma_gemm(const __nv_bfloat16* __restrict__ A,
              const __nv_bfloat16* __restrict__ Bh, const __nv_bfloat16* __restrict__ Bl,
              const float* __restrict__ bias, const float* __restrict__ add1,
              const float* __restrict__ add2, float* __restrict__ C,
              __nv_bfloat16* __restrict__ Cb, int M, int N, int K)
{
    extern __shared__ char smraw[];
    char* sm = (char*)(((uintptr_t)smraw + 1023) & ~(uintptr_t)1023);
    const uint32_t smBase = smem_u32(sm);

    const int tid  = threadIdx.x;
    const int lane = tid & 31, wid = tid >> 5;
    const int wm = (wid & 3) * 32;      // warp m offset in tile
    const int wn = (wid >> 2) * 64;     // warp n offset in tile
    const int m0 = blockIdx.y * 128, n0 = blockIdx.x * 128;

    const size_t strA = (size_t)K * 2;
    const char* gA  = (const char*)A  + (size_t)m0 * strA;
    const char* gBh = (const char*)Bh + (size_t)n0 * strA;
    const char* gBl = (const char*)Bl + (size_t)n0 * strA;

    const int aRow = lane & 15;
    const int aCol = (lane >> 4) * 16;
    const int bRowOff = ((lane & 16) >> 1) + (lane & 7);
    const int bCol = (lane & 8) * 2;

    uint32_t aBase[2], aXor[2];
    #pragma unroll
    for (int mt = 0; mt < 2; mt++) {
        int row = wm + mt * 16 + aRow;
        aBase[mt] = (uint32_t)(row * 128);
        aXor[mt]  = (uint32_t)(aCol ^ ((row & 7) * 16));
    }
    uint32_t bBase[4], bXor[4];
    #pragma unroll
    for (int np = 0; np < 4; np++) {
        int row = wn + np * 16 + bRowOff;
        bBase[np] = (uint32_t)(16384 + row * 128);
        bXor[np]  = (uint32_t)(bCol ^ ((row & 7) * 16));
    }

    float acc[2][8][4];
    #pragma unroll
    for (int i = 0; i < 2; i++)
        #pragma unroll
        for (int j = 0; j < 8; j++)
            #pragma unroll
            for (int k = 0; k < 4; k++) acc[i][j][k] = 0.f;

    const int nCh = K >> 6;

    // stage = 48KB: A @0, Bh @16384, Bl @32768
    #define LOAD_CHUNK(kc_, st_) do {                                           \
        uint32_t dst = smBase + (uint32_t)(st_) * 49152u;                       \
        size_t kb_ = (size_t)(kc_) * 128;                                       \
        _Pragma("unroll")                                                       \
        for (int i_ = 0; i_ < 4; i_++) {                                        \
            int u_ = tid + 256 * i_;                                            \
            int r_ = u_ >> 3, c_ = u_ & 7;                                      \
            uint32_t off_ = (uint32_t)(r_ * 128 + c_ * 16);                     \
            uint32_t sw_ = off_ ^ ((off_ >> 3) & 0x70);                         \
            size_t go_ = (size_t)r_ * strA + kb_ + (size_t)c_ * 16;             \
            cp16(dst + sw_,          gA  + go_);                                \
            cp16(dst + 16384 + sw_,  gBh + go_);                                \
            cp16(dst + 32768 + sw_,  gBl + go_);                                \
        }                                                                       \
    } while (0)

    LOAD_CHUNK(0, 0);
    cp_commit();

    for (int kc = 0; kc < nCh; kc++) {
        const int st = kc & 1;
        cp_wait0();
        __syncthreads();
        if (kc + 1 < nCh) { LOAD_CHUNK(kc + 1, st ^ 1); cp_commit(); }

        const uint32_t stBase = smBase + (uint32_t)st * 49152u;
        #pragma unroll
        for (int ks = 0; ks < 4; ks++) {
            const uint32_t kb = (uint32_t)(ks * 32);
            uint32_t ah[2][4], bh[8][2], bl[8][2];
            #pragma unroll
            for (int mt = 0; mt < 2; mt++) {
                uint32_t ad = stBase + aBase[mt] + (kb ^ aXor[mt]);
                ldm4(ah[mt], ad);
            }
            #pragma unroll
            for (int np = 0; np < 4; np++) {
                uint32_t ad = stBase + bBase[np] + (kb ^ bXor[np]);
                ldm4(&bh[2 * np][0], ad);
                ldm4(&bl[2 * np][0], ad + 16384);
            }
            #pragma unroll
            for (int mt = 0; mt < 2; mt++)
                #pragma unroll
                for (int nt = 0; nt < 8; nt++) mma16816(acc[mt][nt], ah[mt], bh[nt]);
            #pragma unroll
            for (int mt = 0; mt < 2; mt++)
                #pragma unroll
                for (int nt = 0; nt < 8; nt++) mma16816(acc[mt][nt], ah[mt], bl[nt]);
        }
    }
    #undef LOAD_CHUNK

    // epilogue
    #pragma unroll
    for (int mt = 0; mt < 2; mt++) {
        #pragma unroll
        for (int nt = 0; nt < 8; nt++) {
            int row = m0 + wm + mt * 16 + (lane >> 2);
            int col = n0 + wn + nt * 8 + 2 * (lane & 3);
            if (col < N) {
                size_t i0 = (size_t)row * N + col;
                float v0 = acc[mt][nt][0] + bias[col];
                float v1 = acc[mt][nt][1] + bias[col + 1];
                if (add1) { v0 += add1[i0]; v1 += add1[i0 + 1]; }
                if (add2) { v0 += add2[i0]; v1 += add2[i0 + 1]; }
                if (C)  { C[i0] = v0; C[i0 + 1] = v1; }
                if (Cb) { Cb[i0] = __float2bfloat16(v0); Cb[i0 + 1] = __float2bfloat16(v1); }
                size_t i1 = (size_t)(row + 8) * N + col;
                float v2 = acc[mt][nt][2] + bias[col];
                float v3 = acc[mt][nt][3] + bias[col + 1];
                if (add1) { v2 += add1[i1]; v3 += add1[i1 + 1]; }
                if (add2) { v2 += add2[i1]; v3 += add2[i1 + 1]; }
                if (C)  { C[i1] = v2; C[i1 + 1] = v3; }
                if (Cb) { Cb[i1] = __float2bfloat16(v2); Cb[i1 + 1] = __float2bfloat16(v3); }
            }
        }
    }
}

// ---------------- deformable sampling (bf16 v, vectorized x4) ----------------
// block = one (b,q); 192 threads: warp = head, lane*4 = channel quad
__global__ __launch_bounds__(192)
void sample_kernel(const float* __restrict__ refp, const float* __restrict__ off,
                   const float* __restrict__ aw, const __nv_bfloat16* __restrict__ v,
                   __nv_bfloat16* __restrict__ outh)
{
    const int bq = blockIdx.x;
    const int b  = bq / NQ;
    const int tid = threadIdx.x;
    __shared__ float s_off[144], s_w[72], s_x[72], s_y[72], s_ref[6];
    if (tid < 144) s_off[tid] = off[(size_t)bq * 144 + tid];
    if (tid < 72)  s_w[tid]   = aw[(size_t)bq * 72 + tid];
    if (tid < 6)   s_ref[tid] = refp[(size_t)bq * 6 + tid];
    __syncthreads();

    const int Hl[3] = {128, 64, 32};
    const int Wl[3] = {128, 64, 32};
    const int st[3] = {0, 16384, 20480};

    if (tid < 6) {
        int h = tid;
        float mx = -1e30f;
        for (int i = 0; i < 12; i++) mx = fmaxf(mx, s_w[h * 12 + i]);
        float sum = 0.f;
        for (int i = 0; i < 12; i++) { float e = expf(s_w[h * 12 + i] - mx); s_w[h * 12 + i] = e; sum += e; }
        float inv = 1.f / sum;
        for (int i = 0; i < 12; i++) s_w[h * 12 + i] *= inv;
    }
    if (tid < 72) {
        int h = tid / 12, lp = tid % 12, l = lp >> 2, p = lp & 3;
        float ox = s_off[h * 24 + l * 8 + p * 2 + 0];
        float oy = s_off[h * 24 + l * 8 + p * 2 + 1];
        float lx = s_ref[l * 2 + 0] + ox / (float)Wl[l];
        float ly = s_ref[l * 2 + 1] + oy / (float)Hl[l];
        s_x[tid] = lx * (float)Wl[l] - 0.5f;
        s_y[tid] = ly * (float)Hl[l] - 0.5f;
    }
    __syncthreads();

    const int h  = tid >> 5;          // head (warp)
    const int c4 = (tid & 31) * 4;    // channel quad within head
    float a0 = 0.f, a1 = 0.f, a2 = 0.f, a3 = 0.f;
    #pragma unroll
    for (int lp = 0; lp < 12; lp++) {
        const int l  = lp >> 2;
        const int W_ = Wl[l], H_ = Hl[l];
        float w  = s_w[h * 12 + lp];
        float x  = s_x[h * 12 + lp];
        float y  = s_y[h * 12 + lp];
        float x0f = floorf(x), y0f = floorf(y);
        float wx = x - x0f, wy = y - y0f;
        int x0 = (int)x0f, y0 = (int)y0f;
        const __nv_bfloat16* base = v + ((size_t)b * NV + st[l]) * DIM + h * HDIM + c4;
        float w00 = w * (1.f - wx) * (1.f - wy);
        float w10 = w * wx * (1.f - wy);
        float w01 = w * (1.f - wx) * wy;
        float w11 = w * wx * wy;
        #pragma unroll
        for (int cr = 0; cr < 4; cr++) {
            int xi = x0 + (cr & 1), yi = y0 + (cr >> 1);
            float cw = (cr == 0) ? w00 : (cr == 1) ? w10 : (cr == 2) ? w01 : w11;
            if (xi >= 0 && xi < W_ && yi >= 0 && yi < H_ && cw != 0.f) {
                uint2 u = *reinterpret_cast<const uint2*>(base + (size_t)(yi * W_ + xi) * DIM);
                __nv_bfloat162 p0 = *reinterpret_cast<__nv_bfloat162*>(&u.x);
                __nv_bfloat162 p1 = *reinterpret_cast<__nv_bfloat162*>(&u.y);
                a0 += cw * __low2float(p0);
                a1 += cw * __high2float(p0);
                a2 += cw * __low2float(p1);
                a3 += cw * __high2float(p1);
            }
        }
    }
    size_t o = (size_t)bq * DIM + h * HDIM + c4;
    outh[o + 0] = __float2bfloat16(a0);
    outh[o + 1] = __float2bfloat16(a1);
    outh[o + 2] = __float2bfloat16(a2);
    outh[o + 3] = __float2bfloat16(a3);
}

// ---------------- depthwise 3x3 + GELU -> bf16 -------------------------------
__global__ __launch_bounds__(HID)
void dwconv_gelu_kernel(const float* __restrict__ y, const float* __restrict__ w,
                        const float* __restrict__ bias, __nv_bfloat16* __restrict__ outh)
{
    const int bhw = blockIdx.x;
    const int c   = threadIdx.x;
    const int b   = bhw >> 12;
    const int hw  = bhw & 4095;
    const int h   = hw >> 6, ww = hw & 63;
    float acc = bias[c];
    #pragma unroll
    for (int ky = 0; ky < 3; ky++) {
        int hh = h + ky - 1;
        if (hh < 0 || hh >= 64) continue;
        #pragma unroll
        for (int kx = 0; kx < 3; kx++) {
            int xx = ww + kx - 1;
            if (xx < 0 || xx >= 64) continue;
            acc += y[((size_t)(b * 4096 + hh * 64 + xx)) * HID + c] * w[(ky * 3 + kx) * HID + c];
        }
    }
    float g = 0.5f * acc * (1.f + erff(acc * 0.70710678118654752f));
    outh[(size_t)bhw * HID + c] = __float2bfloat16(g);
}

// ---------------- host orchestration ----------------------------------------
#define GEMM_SMEM (98304 + 1024)

extern "C" void kernel_launch(void* const* d_in, const int* in_sizes, int n_in,
                              void* d_out, int out_size)
{
    const float* query = (const float*)d_in[0];
    const float* refp  = (const float*)d_in[1];
    const float* feat  = (const float*)d_in[2];
    const int wb = n_in - 20;
    const float* qn_g  = (const float*)d_in[wb + 0];
    const float* qn_b  = (const float*)d_in[wb + 1];
    const float* fn_g  = (const float*)d_in[wb + 2];
    const float* fn_b  = (const float*)d_in[wb + 3];
    const float* off_w = (const float*)d_in[wb + 4];
    const float* off_b = (const float*)d_in[wb + 5];
    const float* aw_w  = (const float*)d_in[wb + 6];
    const float* aw_b  = (const float*)d_in[wb + 7];
    const float* vp_w  = (const float*)d_in[wb + 8];
    const float* vp_b  = (const float*)d_in[wb + 9];
    const float* op_w  = (const float*)d_in[wb + 10];
    const float* op_b  = (const float*)d_in[wb + 11];
    const float* ffn_g = (const float*)d_in[wb + 12];
    const float* ffn_b = (const float*)d_in[wb + 13];
    const float* fc1_w = (const float*)d_in[wb + 14];
    const float* fc1_b = (const float*)d_in[wb + 15];
    const float* dw_w  = (const float*)d_in[wb + 16];
    const float* dw_b  = (const float*)d_in[wb + 17];
    const float* fc2_w = (const float*)d_in[wb + 18];
    const float* fc2_b = (const float*)d_in[wb + 19];

    static bool attr_done = false;
    if (!attr_done) {
        cudaFuncSetAttribute(mma_gemm, cudaFuncAttributeMaxDynamicSharedMemorySize, GEMM_SMEM);
        attr_done = true;
    }

    float *qf, *off, *aw, *x, *y;
    __nv_bfloat16 *qh, *fnh, *vb, *sph, *xlh, *ygh;
    __nv_bfloat16 *wvh, *wvl, *woh, *wol, *wfh, *wfl, *wah, *wal, *w1h, *w1l, *w2h, *w2l;
    cudaGetSymbolAddress((void**)&qf,  g_qf);  cudaGetSymbolAddress((void**)&qh,  g_qh);
    cudaGetSymbolAddress((void**)&fnh, g_fnh); cudaGetSymbolAddress((void**)&vb,  g_vb);
    cudaGetSymbolAddress((void**)&off, g_off); cudaGetSymbolAddress((void**)&aw,  g_aw);
    cudaGetSymbolAddress((void**)&sph, g_sph); cudaGetSymbolAddress((void**)&x,   g_x);
    cudaGetSymbolAddress((void**)&xlh, g_xlh); cudaGetSymbolAddress((void**)&y,   g_y);
    cudaGetSymbolAddress((void**)&ygh, g_ygh);
    cudaGetSymbolAddress((void**)&wvh, g_wvh); cudaGetSymbolAddress((void**)&wvl, g_wvl);
    cudaGetSymbolAddress((void**)&woh, g_woh); cudaGetSymbolAddress((void**)&wol, g_wol);
    cudaGetSymbolAddress((void**)&wfh, g_wfh); cudaGetSymbolAddress((void**)&wfl, g_wfl);
    cudaGetSymbolAddress((void**)&wah, g_wah); cudaGetSymbolAddress((void**)&wal, g_wal);
    cudaGetSymbolAddress((void**)&w1h, g_w1h); cudaGetSymbolAddress((void**)&w1l, g_w1l);
    cudaGetSymbolAddress((void**)&w2h, g_w2h); cudaGetSymbolAddress((void**)&w2l, g_w2l);

    // launches 0-4, so that launch #5 (ncu -s 5 -c 1) is the dominant vp GEMM
    wprep_kernel<<<(768*768 + 255)/256, 256>>>(vp_w,  wvh, wvl, 768, 768, 768);   // 0
    wprep_kernel<<<(256*768 + 255)/256, 256>>>(off_w, wfh, wfl, 144, 256, 768);   // 1
    wprep_kernel<<<(128*768 + 255)/256, 256>>>(aw_w,  wah, wal, 72,  128, 768);   // 2
    ln_kernel<<<MQ, 256>>>(query, qn_g, qn_b, qf, qh);                            // 3
    ln_kernel<<<MV, 256>>>(feat,  fn_g, fn_b, nullptr, fnh);                      // 4
    // value projection -> bf16 v                                                 // 5
    mma_gemm<<<dim3(6, MV/128), 256, GEMM_SMEM>>>(fnh, wvh, wvl, vp_b, nullptr, nullptr, nullptr, vb, MV, 768, 768);
    // remaining weight preps
    wprep_kernel<<<(768*768 + 255)/256, 256>>>(op_w,  woh, wol, 768, 768, 768);
    wprep_kernel<<<(256*768 + 255)/256, 256>>>(fc1_w, w1h, w1l, 192, 256, 768);
    wprep_kernel<<<(768*192 + 255)/256, 256>>>(fc2_w, w2h, w2l, 768, 768, 192);
    // offsets + attention weights
    mma_gemm<<<dim3(2, MQ/128), 256, GEMM_SMEM>>>(qh, wfh, wfl, off_b, nullptr, nullptr, off, nullptr, MQ, 144, 768);
    mma_gemm<<<dim3(1, MQ/128), 256, GEMM_SMEM>>>(qh, wah, wal, aw_b,  nullptr, nullptr, aw,  nullptr, MQ, 72,  768);
    // sampling (bf16 v -> bf16 samp)
    sample_kernel<<<MQ, 192>>>(refp, off, aw, vb, sph);
    // output projection + residuals: x = query + q + samp@op_w + op_b
    mma_gemm<<<dim3(6, MQ/128), 256, GEMM_SMEM>>>(sph, woh, wol, op_b, qf, query, x, nullptr, MQ, 768, 768);
    // FFN
    ln_kernel<<<MQ, 256>>>(x, ffn_g, ffn_b, nullptr, xlh);
    mma_gemm<<<dim3(2, MQ/128), 256, GEMM_SMEM>>>(xlh, w1h, w1l, fc1_b, nullptr, nullptr, y, nullptr, MQ, 192, 768);
    dwconv_gelu_kernel<<<MQ, HID>>>(y, dw_w, dw_b, ygh);
    // fc2 + final residual into d_out
    mma_gemm<<<dim3(6, MQ/128), 256, GEMM_SMEM>>>(ygh, w2h, w2l, fc2_b, x, nullptr, (float*)d_out, nullptr, MQ, 768, 192);
}

// round 5
// speedup vs baseline: 3.3745x; 1.0065x over previous
#include <cuda_runtime.h>
#include <cuda_fp16.h>
#include <math.h>
#include <stdint.h>

#define DIM    768
#define HEADS  6
#define HDIM   128
#define HID    192
#define BATCH  4
#define NQ     4096
#define NV     21504
#define MQ     (BATCH*NQ)     // 16384
#define MV     (BATCH*NV)     // 86016

// ---------------- helpers ----------------------------------------------------
__device__ __forceinline__ uint32_t smem_u32(const void* p) {
    uint32_t a;
    asm("{ .reg .u64 t; cvta.to.shared.u64 t, %1; cvt.u32.u64 %0, t; }" : "=r"(a) : "l"(p));
    return a;
}
__device__ __forceinline__ void cp16(uint32_t s, const void* g) {
    asm volatile("cp.async.cg.shared.global [%0], [%1], 16;" :: "r"(s), "l"(g));
}
__device__ __forceinline__ void cp_commit() { asm volatile("cp.async.commit_group;"); }
__device__ __forceinline__ void cp_wait0()  { asm volatile("cp.async.wait_group 0;"); }
__device__ __forceinline__ void cp_wait1()  { asm volatile("cp.async.wait_group 1;"); }

__device__ __forceinline__ void ldm4(uint32_t* r, uint32_t a) {
    asm volatile("ldmatrix.sync.aligned.m8n8.x4.shared.b16 {%0,%1,%2,%3}, [%4];"
        : "=r"(r[0]), "=r"(r[1]), "=r"(r[2]), "=r"(r[3]) : "r"(a));
}
__device__ __forceinline__ void mma16816(float* c, const uint32_t* a, const uint32_t* b) {
    asm volatile("mma.sync.aligned.m16n8k16.row.col.f32.f16.f16.f32 "
        "{%0,%1,%2,%3}, {%4,%5,%6,%7}, {%8,%9}, {%0,%1,%2,%3};"
        : "+f"(c[0]), "+f"(c[1]), "+f"(c[2]), "+f"(c[3])
        : "r"(a[0]), "r"(a[1]), "r"(a[2]), "r"(a[3]), "r"(b[0]), "r"(b[1]));
}

// ---------------- scratch ----------------------------------------------------
__device__ __align__(16) float  g_qf  [(size_t)MQ*DIM];
__device__ __align__(16) __half g_qh  [(size_t)MQ*DIM];
__device__ __align__(16) __half g_fnh [(size_t)MV*DIM];
__device__ __align__(16) __half g_vb  [(size_t)MV*DIM];
__device__ __align__(16) float  g_off [(size_t)MQ*144];
__device__ __align__(16) float  g_aw  [(size_t)MQ*72];
__device__ __align__(16) __half g_sph [(size_t)MQ*DIM];
__device__ __align__(16) float  g_x   [(size_t)MQ*DIM];
__device__ __align__(16) __half g_xlh [(size_t)MQ*DIM];
__device__ __align__(16) float  g_y   [(size_t)MQ*HID];
__device__ __align__(16) __half g_ygh [(size_t)MQ*HID];
// pre-transposed fp16 weights [Npad, K]
__device__ __align__(16) __half g_wv[768*768];
__device__ __align__(16) __half g_wo[768*768];
__device__ __align__(16) __half g_wf[256*768];   // off N=144->256
__device__ __align__(16) __half g_wa[128*768];   // aw  N=72 ->128
__device__ __align__(16) __half g_w1[256*768];   // fc1 N=192->256
__device__ __align__(16) __half g_w2[768*192];   // fc2

// ---------------- weight transpose: W[K,N] -> T[Npad,K] fp16 -----------------
__global__ __launch_bounds__(256)
void wprep_kernel(const float* __restrict__ W, __half* __restrict__ T,
                  int N, int Npad, int K)
{
    int idx = blockIdx.x * 256 + threadIdx.x;
    if (idx >= Npad * K) return;
    int n = idx / K, k = idx - n * K;
    float v = (n < N) ? W[(size_t)k * N + n] : 0.f;
    T[idx] = __float2half(v);
}

// ---------------- LayerNorm (768), warp-per-row, float4 ----------------------
__global__ __launch_bounds__(256)
void ln_kernel(const float* __restrict__ in, const float* __restrict__ g,
               const float* __restrict__ b, float* __restrict__ outf,
               __half* __restrict__ outh)
{
    const int row  = blockIdx.x * 8 + (threadIdx.x >> 5);
    const int lane = threadIdx.x & 31;
    const float4* x4 = reinterpret_cast<const float4*>(in + (size_t)row * DIM);
    float4 v[6];
    float s = 0.f, ss = 0.f;
    #pragma unroll
    for (int j = 0; j < 6; j++) {
        v[j] = x4[lane + 32 * j];
        s  += v[j].x + v[j].y + v[j].z + v[j].w;
        ss += v[j].x * v[j].x + v[j].y * v[j].y + v[j].z * v[j].z + v[j].w * v[j].w;
    }
    #pragma unroll
    for (int o = 16; o > 0; o >>= 1) {
        s  += __shfl_xor_sync(0xffffffffu, s,  o);
        ss += __shfl_xor_sync(0xffffffffu, ss, o);
    }
    const float m = s * (1.f / DIM);
    const float r = rsqrtf(ss * (1.f / DIM) - m * m + 1e-6f);
    const float4* g4 = reinterpret_cast<const float4*>(g);
    const float4* b4 = reinterpret_cast<const float4*>(b);
    float4*       f4 = outf ? reinterpret_cast<float4*>(outf + (size_t)row * DIM) : nullptr;
    uint2*        h4 = reinterpret_cast<uint2*>(outh + (size_t)row * DIM);
    #pragma unroll
    for (int j = 0; j < 6; j++) {
        int i = lane + 32 * j;
        float4 gg = g4[i], bb = b4[i];
        float o0 = (v[j].x - m) * r * gg.x + bb.x;
        float o1 = (v[j].y - m) * r * gg.y + bb.y;
        float o2 = (v[j].z - m) * r * gg.z + bb.z;
        float o3 = (v[j].w - m) * r * gg.w + bb.w;
        if (f4) f4[i] = make_float4(o0, o1, o2, o3);
        __half2 p0 = __floats2half2_rn(o0, o1);
        __half2 p1 = __floats2half2_rn(o2, o3);
        uint2 u;
        u.x = *reinterpret_cast<uint32_t*>(&p0);
        u.y = *reinterpret_cast<uint32_t*>(&p1);
        h4[i] = u;
    }
}

// ---------------- fp16 mma.sync GEMM, 3-stage cp.async pipeline --------------
// C = A[M,K] @ B_t[N,K]^T + bias (+add1)(+add2); out fp32 (C) and/or fp16 (Cb).
// CTA tile 128x128, 8 warps (4m x 2n). K-chunk 64. Stage = 32KB (A@0, B@16K).
__global__ __launch_bounds__(256, 2)
void mma_gemm(const __half* __restrict__ A, const __half* __restrict__ B,
              const float* __restrict__ bias, const float* __restrict__ add1,
              const float* __restrict__ add2, float* __restrict__ C,
              __half* __restrict__ Cb, int M, int N, int K)
{
    extern __shared__ char smraw[];
    char* sm = (char*)(((uintptr_t)smraw + 1023) & ~(uintptr_t)1023);
    const uint32_t smBase = smem_u32(sm);

    const int tid  = threadIdx.x;
    const int lane = tid & 31, wid = tid >> 5;
    const int wm = (wid & 3) * 32;
    const int wn = (wid >> 2) * 64;
    const int m0 = blockIdx.y * 128, n0 = blockIdx.x * 128;

    const size_t strA = (size_t)K * 2;
    const char* gA = (const char*)A + (size_t)m0 * strA;
    const char* gB = (const char*)B + (size_t)n0 * strA;

    const int aRow = lane & 15;
    const int aCol = (lane >> 4) * 16;
    const int bRowOff = ((lane & 16) >> 1) + (lane & 7);
    const int bCol = (lane & 8) * 2;

    uint32_t aBase[2], aXor[2];
    #pragma unroll
    for (int mt = 0; mt < 2; mt++) {
        int row = wm + mt * 16 + aRow;
        aBase[mt] = (uint32_t)(row * 128);
        aXor[mt]  = (uint32_t)(aCol ^ ((row & 7) * 16));
    }
    uint32_t bBase[4], bXor[4];
    #pragma unroll
    for (int np = 0; np < 4; np++) {
        int row = wn + np * 16 + bRowOff;
        bBase[np] = (uint32_t)(16384 + row * 128);
        bXor[np]  = (uint32_t)(bCol ^ ((row & 7) * 16));
    }

    float acc[2][8][4];
    #pragma unroll
    for (int i = 0; i < 2; i++)
        #pragma unroll
        for (int j = 0; j < 8; j++)
            #pragma unroll
            for (int k = 0; k < 4; k++) acc[i][j][k] = 0.f;

    const int nCh = K >> 6;

    #define LOAD_CHUNK(kc_, st_) do {                                           \
        uint32_t dst = smBase + (uint32_t)(st_) * 32768u;                       \
        size_t kb_ = (size_t)(kc_) * 128;                                       \
        _Pragma("unroll")                                                       \
        for (int i_ = 0; i_ < 4; i_++) {                                        \
            int u_ = tid + 256 * i_;                                            \
            int r_ = u_ >> 3, c_ = u_ & 7;                                      \
            uint32_t off_ = (uint32_t)(r_ * 128 + c_ * 16);                     \
            uint32_t sw_ = off_ ^ ((off_ >> 3) & 0x70);                         \
            size_t go_ = (size_t)r_ * strA + kb_ + (size_t)c_ * 16;             \
            cp16(dst + sw_,         gA + go_);                                  \
            cp16(dst + 16384 + sw_, gB + go_);                                  \
        }                                                                       \
    } while (0)

    LOAD_CHUNK(0, 0);
    cp_commit();
    if (nCh > 1) { LOAD_CHUNK(1, 1); cp_commit(); }

    for (int kc = 0; kc < nCh; kc++) {
        if (kc + 1 < nCh) cp_wait1(); else cp_wait0();
        __syncthreads();
        if (kc + 2 < nCh) {
            int st2 = (kc + 2) % 3;
            LOAD_CHUNK(kc + 2, st2);
            cp_commit();
        }
        const uint32_t stBase = smBase + (uint32_t)(kc % 3) * 32768u;
        #pragma unroll
        for (int ks = 0; ks < 4; ks++) {
            const uint32_t kb = (uint32_t)(ks * 32);
            uint32_t ah[2][4], bb[8][2];
            #pragma unroll
            for (int mt = 0; mt < 2; mt++)
                ldm4(ah[mt], stBase + aBase[mt] + (kb ^ aXor[mt]));
            #pragma unroll
            for (int np = 0; np < 4; np++)
                ldm4(&bb[2 * np][0], stBase + bBase[np] + (kb ^ bXor[np]));
            #pragma unroll
            for (int mt = 0; mt < 2; mt++)
                #pragma unroll
                for (int nt = 0; nt < 8; nt++) mma16816(acc[mt][nt], ah[mt], bb[nt]);
        }
    }
    #undef LOAD_CHUNK

    // epilogue
    #pragma unroll
    for (int mt = 0; mt < 2; mt++) {
        #pragma unroll
        for (int nt = 0; nt < 8; nt++) {
            int row = m0 + wm + mt * 16 + (lane >> 2);
            int col = n0 + wn + nt * 8 + 2 * (lane & 3);
            if (col < N) {
                size_t i0 = (size_t)row * N + col;
                float v0 = acc[mt][nt][0] + bias[col];
                float v1 = acc[mt][nt][1] + bias[col + 1];
                if (add1) { v0 += add1[i0]; v1 += add1[i0 + 1]; }
                if (add2) { v0 += add2[i0]; v1 += add2[i0 + 1]; }
                if (C)  { C[i0] = v0; C[i0 + 1] = v1; }
                if (Cb) { Cb[i0] = __float2half(v0); Cb[i0 + 1] = __float2half(v1); }
                size_t i1 = (size_t)(row + 8) * N + col;
                float v2 = acc[mt][nt][2] + bias[col];
                float v3 = acc[mt][nt][3] + bias[col + 1];
                if (add1) { v2 += add1[i1]; v3 += add1[i1 + 1]; }
                if (add2) { v2 += add2[i1]; v3 += add2[i1 + 1]; }
                if (C)  { C[i1] = v2; C[i1 + 1] = v3; }
                if (Cb) { Cb[i1] = __float2half(v2); Cb[i1 + 1] = __float2half(v3); }
            }
        }
    }
}

// ---------------- deformable sampling (fp16 v, vectorized x4) ----------------
__global__ __launch_bounds__(192)
void sample_kernel(const float* __restrict__ refp, const float* __restrict__ off,
                   const float* __restrict__ aw, const __half* __restrict__ v,
                   __half* __restrict__ outh)
{
    const int bq = blockIdx.x;
    const int b  = bq / NQ;
    const int tid = threadIdx.x;
    __shared__ float s_off[144], s_w[72], s_x[72], s_y[72], s_ref[6];
    if (tid < 144) s_off[tid] = off[(size_t)bq * 144 + tid];
    if (tid < 72)  s_w[tid]   = aw[(size_t)bq * 72 + tid];
    if (tid < 6)   s_ref[tid] = refp[(size_t)bq * 6 + tid];
    __syncthreads();

    const int Hl[3] = {128, 64, 32};
    const int Wl[3] = {128, 64, 32};
    const int st[3] = {0, 16384, 20480};

    if (tid < 6) {
        int h = tid;
        float mx = -1e30f;
        for (int i = 0; i < 12; i++) mx = fmaxf(mx, s_w[h * 12 + i]);
        float sum = 0.f;
        for (int i = 0; i < 12; i++) { float e = expf(s_w[h * 12 + i] - mx); s_w[h * 12 + i] = e; sum += e; }
        float inv = 1.f / sum;
        for (int i = 0; i < 12; i++) s_w[h * 12 + i] *= inv;
    }
    if (tid < 72) {
        int h = tid / 12, lp = tid % 12, l = lp >> 2, p = lp & 3;
        float ox = s_off[h * 24 + l * 8 + p * 2 + 0];
        float oy = s_off[h * 24 + l * 8 + p * 2 + 1];
        float lx = s_ref[l * 2 + 0] + ox / (float)Wl[l];
        float ly = s_ref[l * 2 + 1] + oy / (float)Hl[l];
        s_x[tid] = lx * (float)Wl[l] - 0.5f;
        s_y[tid] = ly * (float)Hl[l] - 0.5f;
    }
    __syncthreads();

    const int h  = tid >> 5;
    const int c4 = (tid & 31) * 4;
    float a0 = 0.f, a1 = 0.f, a2 = 0.f, a3 = 0.f;
    #pragma unroll
    for (int lp = 0; lp < 12; lp++) {
        const int l  = lp >> 2;
        const int W_ = Wl[l], H_ = Hl[l];
        float w  = s_w[h * 12 + lp];
        float x  = s_x[h * 12 + lp];
        float y  = s_y[h * 12 + lp];
        float x0f = floorf(x), y0f = floorf(y);
        float wx = x - x0f, wy = y - y0f;
        int x0 = (int)x0f, y0 = (int)y0f;
        const __half* base = v + ((size_t)b * NV + st[l]) * DIM + h * HDIM + c4;
        float w00 = w * (1.f - wx) * (1.f - wy);
        float w10 = w * wx * (1.f - wy);
        float w01 = w * (1.f - wx) * wy;
        float w11 = w * wx * wy;
        #pragma unroll
        for (int cr = 0; cr < 4; cr++) {
            int xi = x0 + (cr & 1), yi = y0 + (cr >> 1);
            float cw = (cr == 0) ? w00 : (cr == 1) ? w10 : (cr == 2) ? w01 : w11;
            if (xi >= 0 && xi < W_ && yi >= 0 && yi < H_ && cw != 0.f) {
                uint2 u = *reinterpret_cast<const uint2*>(base + (size_t)(yi * W_ + xi) * DIM);
                float2 p0 = __half22float2(*reinterpret_cast<__half2*>(&u.x));
                float2 p1 = __half22float2(*reinterpret_cast<__half2*>(&u.y));
                a0 += cw * p0.x;
                a1 += cw * p0.y;
                a2 += cw * p1.x;
                a3 += cw * p1.y;
            }
        }
    }
    size_t o = (size_t)bq * DIM + h * HDIM + c4;
    __half2 q0 = __floats2half2_rn(a0, a1);
    __half2 q1 = __floats2half2_rn(a2, a3);
    uint2 u;
    u.x = *reinterpret_cast<uint32_t*>(&q0);
    u.y = *reinterpret_cast<uint32_t*>(&q1);
    *reinterpret_cast<uint2*>(outh + o) = u;
}

// ---------------- depthwise 3x3 + GELU -> fp16 --------------------------------
__global__ __launch_bounds__(HID)
void dwconv_gelu_kernel(const float* __restrict__ y, const float* __restrict__ w,
                        const float* __restrict__ bias, __half* __restrict__ outh)
{
    const int bhw = blockIdx.x;
    const int c   = threadIdx.x;
    const int b   = bhw >> 12;
    const int hw  = bhw & 4095;
    const int h   = hw >> 6, ww = hw & 63;
    float acc = bias[c];
    #pragma unroll
    for (int ky = 0; ky < 3; ky++) {
        int hh = h + ky - 1;
        if (hh < 0 || hh >= 64) continue;
        #pragma unroll
        for (int kx = 0; kx < 3; kx++) {
            int xx = ww + kx - 1;
            if (xx < 0 || xx >= 64) continue;
            acc += y[((size_t)(b * 4096 + hh * 64 + xx)) * HID + c] * w[(ky * 3 + kx) * HID + c];
        }
    }
    float g = 0.5f * acc * (1.f + erff(acc * 0.70710678118654752f));
    outh[(size_t)bhw * HID + c] = __float2half(g);
}

// ---------------- host orchestration ----------------------------------------
#define GEMM_SMEM (98304 + 1024)

extern "C" void kernel_launch(void* const* d_in, const int* in_sizes, int n_in,
                              void* d_out, int out_size)
{
    const float* query = (const float*)d_in[0];
    const float* refp  = (const float*)d_in[1];
    const float* feat  = (const float*)d_in[2];
    const int wb = n_in - 20;
    const float* qn_g  = (const float*)d_in[wb + 0];
    const float* qn_b  = (const float*)d_in[wb + 1];
    const float* fn_g  = (const float*)d_in[wb + 2];
    const float* fn_b  = (const float*)d_in[wb + 3];
    const float* off_w = (const float*)d_in[wb + 4];
    const float* off_b = (const float*)d_in[wb + 5];
    const float* aw_w  = (const float*)d_in[wb + 6];
    const float* aw_b  = (const float*)d_in[wb + 7];
    const float* vp_w  = (const float*)d_in[wb + 8];
    const float* vp_b  = (const float*)d_in[wb + 9];
    const float* op_w  = (const float*)d_in[wb + 10];
    const float* op_b  = (const float*)d_in[wb + 11];
    const float* ffn_g = (const float*)d_in[wb + 12];
    const float* ffn_b = (const float*)d_in[wb + 13];
    const float* fc1_w = (const float*)d_in[wb + 14];
    const float* fc1_b = (const float*)d_in[wb + 15];
    const float* dw_w  = (const float*)d_in[wb + 16];
    const float* dw_b  = (const float*)d_in[wb + 17];
    const float* fc2_w = (const float*)d_in[wb + 18];
    const float* fc2_b = (const float*)d_in[wb + 19];

    static bool attr_done = false;
    if (!attr_done) {
        cudaFuncSetAttribute(mma_gemm, cudaFuncAttributeMaxDynamicSharedMemorySize, GEMM_SMEM);
        attr_done = true;
    }

    float *qf, *off, *aw, *x, *y;
    __half *qh, *fnh, *vb, *sph, *xlh, *ygh;
    __half *wv, *wo, *wf, *wa, *w1, *w2;
    cudaGetSymbolAddress((void**)&qf,  g_qf);  cudaGetSymbolAddress((void**)&qh,  g_qh);
    cudaGetSymbolAddress((void**)&fnh, g_fnh); cudaGetSymbolAddress((void**)&vb,  g_vb);
    cudaGetSymbolAddress((void**)&off, g_off); cudaGetSymbolAddress((void**)&aw,  g_aw);
    cudaGetSymbolAddress((void**)&sph, g_sph); cudaGetSymbolAddress((void**)&x,   g_x);
    cudaGetSymbolAddress((void**)&xlh, g_xlh); cudaGetSymbolAddress((void**)&y,   g_y);
    cudaGetSymbolAddress((void**)&ygh, g_ygh);
    cudaGetSymbolAddress((void**)&wv, g_wv); cudaGetSymbolAddress((void**)&wo, g_wo);
    cudaGetSymbolAddress((void**)&wf, g_wf); cudaGetSymbolAddress((void**)&wa, g_wa);
    cudaGetSymbolAddress((void**)&w1, g_w1); cudaGetSymbolAddress((void**)&w2, g_w2);

    // launches 0-4 chosen so launch #5 (ncu -s 5 -c 1) is the dominant vp GEMM
    wprep_kernel<<<(768*768 + 255)/256, 256>>>(vp_w,  wv, 768, 768, 768);   // 0
    wprep_kernel<<<(256*768 + 255)/256, 256>>>(off_w, wf, 144, 256, 768);   // 1
    wprep_kernel<<<(128*768 + 255)/256, 256>>>(aw_w,  wa, 72,  128, 768);   // 2
    ln_kernel<<<MQ/8, 256>>>(query, qn_g, qn_b, qf, qh);                    // 3
    ln_kernel<<<MV/8, 256>>>(feat,  fn_g, fn_b, nullptr, fnh);              // 4
    // value projection -> fp16 v                                            // 5
    mma_gemm<<<dim3(6, MV/128), 256, GEMM_SMEM>>>(fnh, wv, vp_b, nullptr, nullptr, nullptr, vb, MV, 768, 768);
    // remaining weight preps
    wprep_kernel<<<(768*768 + 255)/256, 256>>>(op_w,  wo, 768, 768, 768);
    wprep_kernel<<<(256*768 + 255)/256, 256>>>(fc1_w, w1, 192, 256, 768);
    wprep_kernel<<<(768*192 + 255)/256, 256>>>(fc2_w, w2, 768, 768, 192);
    // offsets + attention weights
    mma_gemm<<<dim3(2, MQ/128), 256, GEMM_SMEM>>>(qh, wf, off_b, nullptr, nullptr, off, nullptr, MQ, 144, 768);
    mma_gemm<<<dim3(1, MQ/128), 256, GEMM_SMEM>>>(qh, wa, aw_b,  nullptr, nullptr, aw,  nullptr, MQ, 72,  768);
    // sampling
    sample_kernel<<<MQ, 192>>>(refp, off, aw, vb, sph);
    // output projection + residuals: x = query + q + samp@op_w + op_b
    mma_gemm<<<dim3(6, MQ/128), 256, GEMM_SMEM>>>(sph, wo, op_b, qf, query, x, nullptr, MQ, 768, 768);
    // FFN
    ln_kernel<<<MQ/8, 256>>>(x, ffn_g, ffn_b, nullptr, xlh);
    mma_gemm<<<dim3(2, MQ/128), 256, GEMM_SMEM>>>(xlh, w1, fc1_b, nullptr, nullptr, y, nullptr, MQ, 192, 768);
    dwconv_gelu_kernel<<<MQ, HID>>>(y, dw_w, dw_b, ygh);
    // fc2 + final residual into d_out
    mma_gemm<<<dim3(6, MQ/128), 256, GEMM_SMEM>>>(ygh, w2, fc2_b, x, nullptr, (float*)d_out, nullptr, MQ, 768, 192);
}

// round 6
// speedup vs baseline: 5.1911x; 1.5383x over previous
#include <cuda_runtime.h>
#include <cuda_fp16.h>
#include <math.h>
#include <stdint.h>

#define DIM    768
#define HEADS  6
#define HDIM   128
#define HID    192
#define BATCH  4
#define NQ     4096
#define NV     21504
#define MQ     (BATCH*NQ)     // 16384
#define MV     (BATCH*NV)     // 86016
#define NFA    216            // merged off(144)+aw(72) output cols

// ---------------- helpers ----------------------------------------------------
__device__ __forceinline__ uint32_t smem_u32(const void* p) {
    uint32_t a;
    asm("{ .reg .u64 t; cvta.to.shared.u64 t, %1; cvt.u32.u64 %0, t; }" : "=r"(a) : "l"(p));
    return a;
}
__device__ __forceinline__ void cp16(uint32_t s, const void* g) {
    asm volatile("cp.async.cg.shared.global [%0], [%1], 16;" :: "r"(s), "l"(g));
}
__device__ __forceinline__ void cp_commit() { asm volatile("cp.async.commit_group;"); }
__device__ __forceinline__ void cp_wait0()  { asm volatile("cp.async.wait_group 0;"); }
__device__ __forceinline__ void cp_wait1()  { asm volatile("cp.async.wait_group 1;"); }

__device__ __forceinline__ void ldm4(uint32_t* r, uint32_t a) {
    asm volatile("ldmatrix.sync.aligned.m8n8.x4.shared.b16 {%0,%1,%2,%3}, [%4];"
        : "=r"(r[0]), "=r"(r[1]), "=r"(r[2]), "=r"(r[3]) : "r"(a));
}
__device__ __forceinline__ void mma16816(float* c, const uint32_t* a, const uint32_t* b) {
    asm volatile("mma.sync.aligned.m16n8k16.row.col.f32.f16.f16.f32 "
        "{%0,%1,%2,%3}, {%4,%5,%6,%7}, {%8,%9}, {%0,%1,%2,%3};"
        : "+f"(c[0]), "+f"(c[1]), "+f"(c[2]), "+f"(c[3])
        : "r"(a[0]), "r"(a[1]), "r"(a[2]), "r"(a[3]), "r"(b[0]), "r"(b[1]));
}

// ---------------- scratch ----------------------------------------------------
__device__ __align__(16) float  g_qf  [(size_t)MQ*DIM];
__device__ __align__(16) __half g_qh  [(size_t)MQ*DIM];
__device__ __align__(16) __half g_fnh [(size_t)MV*DIM];
__device__ __align__(16) __half g_vb  [(size_t)MV*DIM];
__device__ __align__(16) float  g_fa  [(size_t)MQ*NFA];   // merged off|aw
__device__ __align__(16) float  g_fab [256];              // merged bias
__device__ __align__(16) __half g_sph [(size_t)MQ*DIM];
__device__ __align__(16) float  g_x   [(size_t)MQ*DIM];
__device__ __align__(16) __half g_xlh [(size_t)MQ*DIM];
__device__ __align__(16) float  g_y   [(size_t)MQ*HID];
__device__ __align__(16) __half g_ygh [(size_t)MQ*HID];
// pre-transposed fp16 weights [Npad, K]
__device__ __align__(16) __half g_wv [768*768];
__device__ __align__(16) __half g_wo [768*768];
__device__ __align__(16) __half g_wfa[256*768];   // merged off+aw, N=216 -> 256
__device__ __align__(16) __half g_w1 [256*768];   // fc1 N=192 -> 256
__device__ __align__(16) __half g_w2 [768*192];   // fc2

// ---------------- weight transpose: W[K,N] -> T[Npad,K] fp16 -----------------
__global__ __launch_bounds__(256)
void wprep_kernel(const float* __restrict__ W, __half* __restrict__ T,
                  int N, int Npad, int K)
{
    int idx = blockIdx.x * 256 + threadIdx.x;
    if (idx >= Npad * K) return;
    int n = idx / K, k = idx - n * K;
    float v = (n < N) ? W[(size_t)k * N + n] : 0.f;
    T[idx] = __float2half(v);
}

// merged off(144)+aw(72) -> [256, 768]
__global__ __launch_bounds__(256)
void wprep_merged_kernel(const float* __restrict__ Woff, const float* __restrict__ Waw,
                         __half* __restrict__ T)
{
    int idx = blockIdx.x * 256 + threadIdx.x;
    if (idx >= 256 * 768) return;
    int n = idx / 768, k = idx - n * 768;
    float v = 0.f;
    if (n < 144)      v = Woff[(size_t)k * 144 + n];
    else if (n < 216) v = Waw [(size_t)k * 72 + (n - 144)];
    T[idx] = __float2half(v);
}
__global__ void biascat_kernel(const float* __restrict__ ob, const float* __restrict__ ab,
                               float* __restrict__ out)
{
    int i = threadIdx.x;
    out[i] = (i < 144) ? ob[i] : (i < 216 ? ab[i - 144] : 0.f);
}

// ---------------- LayerNorm (768), warp-per-row, float4 ----------------------
__global__ __launch_bounds__(256)
void ln_kernel(const float* __restrict__ in, const float* __restrict__ g,
               const float* __restrict__ b, float* __restrict__ outf,
               __half* __restrict__ outh)
{
    const int row  = blockIdx.x * 8 + (threadIdx.x >> 5);
    const int lane = threadIdx.x & 31;
    const float4* x4 = reinterpret_cast<const float4*>(in + (size_t)row * DIM);
    float4 v[6];
    float s = 0.f, ss = 0.f;
    #pragma unroll
    for (int j = 0; j < 6; j++) {
        v[j] = x4[lane + 32 * j];
        s  += v[j].x + v[j].y + v[j].z + v[j].w;
        ss += v[j].x * v[j].x + v[j].y * v[j].y + v[j].z * v[j].z + v[j].w * v[j].w;
    }
    #pragma unroll
    for (int o = 16; o > 0; o >>= 1) {
        s  += __shfl_xor_sync(0xffffffffu, s,  o);
        ss += __shfl_xor_sync(0xffffffffu, ss, o);
    }
    const float m = s * (1.f / DIM);
    const float r = rsqrtf(ss * (1.f / DIM) - m * m + 1e-6f);
    const float4* g4 = reinterpret_cast<const float4*>(g);
    const float4* b4 = reinterpret_cast<const float4*>(b);
    float4*       f4 = outf ? reinterpret_cast<float4*>(outf + (size_t)row * DIM) : nullptr;
    uint2*        h4 = reinterpret_cast<uint2*>(outh + (size_t)row * DIM);
    #pragma unroll
    for (int j = 0; j < 6; j++) {
        int i = lane + 32 * j;
        float4 gg = g4[i], bb = b4[i];
        float o0 = (v[j].x - m) * r * gg.x + bb.x;
        float o1 = (v[j].y - m) * r * gg.y + bb.y;
        float o2 = (v[j].z - m) * r * gg.z + bb.z;
        float o3 = (v[j].w - m) * r * gg.w + bb.w;
        if (f4) f4[i] = make_float4(o0, o1, o2, o3);
        __half2 p0 = __floats2half2_rn(o0, o1);
        __half2 p1 = __floats2half2_rn(o2, o3);
        uint2 u;
        u.x = *reinterpret_cast<uint32_t*>(&p0);
        u.y = *reinterpret_cast<uint32_t*>(&p1);
        h4[i] = u;
    }
}

// ---------------- fp16 mma.sync GEMM, 3-stage cp.async pipeline --------------
// C[row, col] at leading-dim ldc. B_t [Npad, K] pre-transposed.
__global__ __launch_bounds__(256, 2)
void mma_gemm(const __half* __restrict__ A, const __half* __restrict__ B,
              const float* __restrict__ bias, const float* __restrict__ add1,
              const float* __restrict__ add2, float* __restrict__ C,
              __half* __restrict__ Cb, int M, int N, int ldc, int K)
{
    extern __shared__ char smraw[];
    char* sm = (char*)(((uintptr_t)smraw + 1023) & ~(uintptr_t)1023);
    const uint32_t smBase = smem_u32(sm);

    const int tid  = threadIdx.x;
    const int lane = tid & 31, wid = tid >> 5;
    const int wm = (wid & 3) * 32;
    const int wn = (wid >> 2) * 64;
    const int m0 = blockIdx.y * 128, n0 = blockIdx.x * 128;

    const size_t strA = (size_t)K * 2;
    const char* gA = (const char*)A + (size_t)m0 * strA;
    const char* gB = (const char*)B + (size_t)n0 * strA;

    const int aRow = lane & 15;
    const int aCol = (lane >> 4) * 16;
    const int bRowOff = ((lane & 16) >> 1) + (lane & 7);
    const int bCol = (lane & 8) * 2;

    uint32_t aBase[2], aXor[2];
    #pragma unroll
    for (int mt = 0; mt < 2; mt++) {
        int row = wm + mt * 16 + aRow;
        aBase[mt] = (uint32_t)(row * 128);
        aXor[mt]  = (uint32_t)(aCol ^ ((row & 7) * 16));
    }
    uint32_t bBase[4], bXor[4];
    #pragma unroll
    for (int np = 0; np < 4; np++) {
        int row = wn + np * 16 + bRowOff;
        bBase[np] = (uint32_t)(16384 + row * 128);
        bXor[np]  = (uint32_t)(bCol ^ ((row & 7) * 16));
    }

    float acc[2][8][4];
    #pragma unroll
    for (int i = 0; i < 2; i++)
        #pragma unroll
        for (int j = 0; j < 8; j++)
            #pragma unroll
            for (int k = 0; k < 4; k++) acc[i][j][k] = 0.f;

    const int nCh = K >> 6;

    #define LOAD_CHUNK(kc_, st_) do {                                           \
        uint32_t dst = smBase + (uint32_t)(st_) * 32768u;                       \
        size_t kb_ = (size_t)(kc_) * 128;                                       \
        _Pragma("unroll")                                                       \
        for (int i_ = 0; i_ < 4; i_++) {                                        \
            int u_ = tid + 256 * i_;                                            \
            int r_ = u_ >> 3, c_ = u_ & 7;                                      \
            uint32_t off_ = (uint32_t)(r_ * 128 + c_ * 16);                     \
            uint32_t sw_ = off_ ^ ((off_ >> 3) & 0x70);                         \
            size_t go_ = (size_t)r_ * strA + kb_ + (size_t)c_ * 16;             \
            cp16(dst + sw_,         gA + go_);                                  \
            cp16(dst + 16384 + sw_, gB + go_);                                  \
        }                                                                       \
    } while (0)

    LOAD_CHUNK(0, 0);
    cp_commit();
    if (nCh > 1) { LOAD_CHUNK(1, 1); cp_commit(); }

    for (int kc = 0; kc < nCh; kc++) {
        if (kc + 1 < nCh) cp_wait1(); else cp_wait0();
        __syncthreads();
        if (kc + 2 < nCh) {
            int st2 = (kc + 2) % 3;
            LOAD_CHUNK(kc + 2, st2);
            cp_commit();
        }
        const uint32_t stBase = smBase + (uint32_t)(kc % 3) * 32768u;
        #pragma unroll
        for (int ks = 0; ks < 4; ks++) {
            const uint32_t kb = (uint32_t)(ks * 32);
            uint32_t ah[2][4], bb[8][2];
            #pragma unroll
            for (int mt = 0; mt < 2; mt++)
                ldm4(ah[mt], stBase + aBase[mt] + (kb ^ aXor[mt]));
            #pragma unroll
            for (int np = 0; np < 4; np++)
                ldm4(&bb[2 * np][0], stBase + bBase[np] + (kb ^ bXor[np]));
            #pragma unroll
            for (int mt = 0; mt < 2; mt++)
                #pragma unroll
                for (int nt = 0; nt < 8; nt++) mma16816(acc[mt][nt], ah[mt], bb[nt]);
        }
    }
    #undef LOAD_CHUNK

    // epilogue
    #pragma unroll
    for (int mt = 0; mt < 2; mt++) {
        #pragma unroll
        for (int nt = 0; nt < 8; nt++) {
            int row = m0 + wm + mt * 16 + (lane >> 2);
            int col = n0 + wn + nt * 8 + 2 * (lane & 3);
            if (col < N) {
                size_t i0 = (size_t)row * ldc + col;
                float v0 = acc[mt][nt][0] + bias[col];
                float v1 = acc[mt][nt][1] + bias[col + 1];
                if (add1) { v0 += add1[i0]; v1 += add1[i0 + 1]; }
                if (add2) { v0 += add2[i0]; v1 += add2[i0 + 1]; }
                if (C)  { C[i0] = v0; C[i0 + 1] = v1; }
                if (Cb) { Cb[i0] = __float2half(v0); Cb[i0 + 1] = __float2half(v1); }
                size_t i1 = (size_t)(row + 8) * ldc + col;
                float v2 = acc[mt][nt][2] + bias[col];
                float v3 = acc[mt][nt][3] + bias[col + 1];
                if (add1) { v2 += add1[i1]; v3 += add1[i1 + 1]; }
                if (add2) { v2 += add2[i1]; v3 += add2[i1 + 1]; }
                if (C)  { C[i1] = v2; C[i1 + 1] = v3; }
                if (Cb) { Cb[i1] = __float2half(v2); Cb[i1 + 1] = __float2half(v3); }
            }
        }
    }
}

// ---------------- deformable sampling: 2 queries/block, fp16 v ---------------
__global__ __launch_bounds__(384)
void sample_kernel(const float* __restrict__ refp, const float* __restrict__ fa,
                   const __half* __restrict__ v, __half* __restrict__ outh)
{
    const int slot = threadIdx.x / 192;
    const int sub  = threadIdx.x % 192;
    const int bq   = blockIdx.x * 2 + slot;
    const int b    = bq / NQ;
    __shared__ float s_fa[2][NFA], s_w[2][72], s_x[2][72], s_y[2][72], s_ref[2][6];
    for (int i = sub; i < NFA; i += 192) s_fa[slot][i] = fa[(size_t)bq * NFA + i];
    if (sub < 6) s_ref[slot][sub] = refp[(size_t)bq * 6 + sub];
    __syncthreads();

    const int Hl[3] = {128, 64, 32};
    const int Wl[3] = {128, 64, 32};
    const int st[3] = {0, 16384, 20480};

    if (sub < 6) {  // softmax over aw part (s_fa[144:216])
        int h = sub;
        const float* wrow = &s_fa[slot][144 + h * 12];
        float mx = -1e30f;
        for (int i = 0; i < 12; i++) mx = fmaxf(mx, wrow[i]);
        float sum = 0.f;
        float e[12];
        for (int i = 0; i < 12; i++) { e[i] = expf(wrow[i] - mx); sum += e[i]; }
        float inv = 1.f / sum;
        for (int i = 0; i < 12; i++) s_w[slot][h * 12 + i] = e[i] * inv;
    }
    if (sub < 72) {
        int h = sub / 12, lp = sub % 12, l = lp >> 2, p = lp & 3;
        float ox = s_fa[slot][h * 24 + l * 8 + p * 2 + 0];
        float oy = s_fa[slot][h * 24 + l * 8 + p * 2 + 1];
        float lx = s_ref[slot][l * 2 + 0] + ox / (float)Wl[l];
        float ly = s_ref[slot][l * 2 + 1] + oy / (float)Hl[l];
        s_x[slot][sub] = lx * (float)Wl[l] - 0.5f;
        s_y[slot][sub] = ly * (float)Hl[l] - 0.5f;
    }
    __syncthreads();

    const int h  = sub >> 5;
    const int c4 = (sub & 31) * 4;
    float a0 = 0.f, a1 = 0.f, a2 = 0.f, a3 = 0.f;
    #pragma unroll
    for (int lp = 0; lp < 12; lp++) {
        const int l  = lp >> 2;
        const int W_ = Wl[l], H_ = Hl[l];
        float w  = s_w[slot][h * 12 + lp];
        float x  = s_x[slot][h * 12 + lp];
        float y  = s_y[slot][h * 12 + lp];
        float x0f = floorf(x), y0f = floorf(y);
        float wx = x - x0f, wy = y - y0f;
        int x0 = (int)x0f, y0 = (int)y0f;
        const __half* base = v + ((size_t)b * NV + st[l]) * DIM + h * HDIM + c4;
        float w00 = w * (1.f - wx) * (1.f - wy);
        float w10 = w * wx * (1.f - wy);
        float w01 = w * (1.f - wx) * wy;
        float w11 = w * wx * wy;
        #pragma unroll
        for (int cr = 0; cr < 4; cr++) {
            int xi = x0 + (cr & 1), yi = y0 + (cr >> 1);
            float cw = (cr == 0) ? w00 : (cr == 1) ? w10 : (cr == 2) ? w01 : w11;
            if (xi >= 0 && xi < W_ && yi >= 0 && yi < H_ && cw != 0.f) {
                uint2 u = *reinterpret_cast<const uint2*>(base + (size_t)(yi * W_ + xi) * DIM);
                float2 p0 = __half22float2(*reinterpret_cast<__half2*>(&u.x));
                float2 p1 = __half22float2(*reinterpret_cast<__half2*>(&u.y));
                a0 += cw * p0.x;
                a1 += cw * p0.y;
                a2 += cw * p1.x;
                a3 += cw * p1.y;
            }
        }
    }
    size_t o = (size_t)bq * DIM + h * HDIM + c4;
    __half2 q0 = __floats2half2_rn(a0, a1);
    __half2 q1 = __floats2half2_rn(a2, a3);
    uint2 u;
    u.x = *reinterpret_cast<uint32_t*>(&q0);
    u.y = *reinterpret_cast<uint32_t*>(&q1);
    *reinterpret_cast<uint2*>(outh + o) = u;
}

// ---------------- depthwise 3x3 + GELU -> fp16 --------------------------------
__global__ __launch_bounds__(HID)
void dwconv_gelu_kernel(const float* __restrict__ y, const float* __restrict__ w,
                        const float* __restrict__ bias, __half* __restrict__ outh)
{
    const int bhw = blockIdx.x;
    const int c   = threadIdx.x;
    const int b   = bhw >> 12;
    const int hw  = bhw & 4095;
    const int h   = hw >> 6, ww = hw & 63;
    float acc = bias[c];
    #pragma unroll
    for (int ky = 0; ky < 3; ky++) {
        int hh = h + ky - 1;
        if (hh < 0 || hh >= 64) continue;
        #pragma unroll
        for (int kx = 0; kx < 3; kx++) {
            int xx = ww + kx - 1;
            if (xx < 0 || xx >= 64) continue;
            acc += y[((size_t)(b * 4096 + hh * 64 + xx)) * HID + c] * w[(ky * 3 + kx) * HID + c];
        }
    }
    float g = 0.5f * acc * (1.f + erff(acc * 0.70710678118654752f));
    outh[(size_t)bhw * HID + c] = __float2half(g);
}

// ---------------- host orchestration ----------------------------------------
#define GEMM_SMEM (98304 + 1024)

extern "C" void kernel_launch(void* const* d_in, const int* in_sizes, int n_in,
                              void* d_out, int out_size)
{
    const float* query = (const float*)d_in[0];
    const float* refp  = (const float*)d_in[1];
    const float* feat  = (const float*)d_in[2];
    const int wb = n_in - 20;
    const float* qn_g  = (const float*)d_in[wb + 0];
    const float* qn_b  = (const float*)d_in[wb + 1];
    const float* fn_g  = (const float*)d_in[wb + 2];
    const float* fn_b  = (const float*)d_in[wb + 3];
    const float* off_w = (const float*)d_in[wb + 4];
    const float* off_b = (const float*)d_in[wb + 5];
    const float* aw_w  = (const float*)d_in[wb + 6];
    const float* aw_b  = (const float*)d_in[wb + 7];
    const float* vp_w  = (const float*)d_in[wb + 8];
    const float* vp_b  = (const float*)d_in[wb + 9];
    const float* op_w  = (const float*)d_in[wb + 10];
    const float* op_b  = (const float*)d_in[wb + 11];
    const float* ffn_g = (const float*)d_in[wb + 12];
    const float* ffn_b = (const float*)d_in[wb + 13];
    const float* fc1_w = (const float*)d_in[wb + 14];
    const float* fc1_b = (const float*)d_in[wb + 15];
    const float* dw_w  = (const float*)d_in[wb + 16];
    const float* dw_b  = (const float*)d_in[wb + 17];
    const float* fc2_w = (const float*)d_in[wb + 18];
    const float* fc2_b = (const float*)d_in[wb + 19];

    static cudaStream_t s1 = nullptr, s2 = nullptr;
    static cudaEvent_t e0, e0b, ev, ew;
    if (!s1) {
        cudaStreamCreateWithFlags(&s1, cudaStreamNonBlocking);
        cudaStreamCreateWithFlags(&s2, cudaStreamNonBlocking);
        cudaEventCreateWithFlags(&e0,  cudaEventDisableTiming);
        cudaEventCreateWithFlags(&e0b, cudaEventDisableTiming);
        cudaEventCreateWithFlags(&ev,  cudaEventDisableTiming);
        cudaEventCreateWithFlags(&ew,  cudaEventDisableTiming);
        cudaFuncSetAttribute(mma_gemm, cudaFuncAttributeMaxDynamicSharedMemorySize, GEMM_SMEM);
    }

    float *qf, *fa, *fab, *x, *y;
    __half *qh, *fnh, *vb, *sph, *xlh, *ygh;
    __half *wv, *wo, *wfa, *w1, *w2;
    cudaGetSymbolAddress((void**)&qf,  g_qf);  cudaGetSymbolAddress((void**)&qh,  g_qh);
    cudaGetSymbolAddress((void**)&fnh, g_fnh); cudaGetSymbolAddress((void**)&vb,  g_vb);
    cudaGetSymbolAddress((void**)&fa,  g_fa);  cudaGetSymbolAddress((void**)&fab, g_fab);
    cudaGetSymbolAddress((void**)&sph, g_sph); cudaGetSymbolAddress((void**)&x,   g_x);
    cudaGetSymbolAddress((void**)&xlh, g_xlh); cudaGetSymbolAddress((void**)&y,   g_y);
    cudaGetSymbolAddress((void**)&ygh, g_ygh);
    cudaGetSymbolAddress((void**)&wv,  g_wv);  cudaGetSymbolAddress((void**)&wo,  g_wo);
    cudaGetSymbolAddress((void**)&wfa, g_wfa); cudaGetSymbolAddress((void**)&w1,  g_w1);
    cudaGetSymbolAddress((void**)&w2,  g_w2);

    // fork
    cudaEventRecord(e0, 0);
    cudaStreamWaitEvent(s1, e0, 0);
    cudaStreamWaitEvent(s2, e0, 0);

    // s1: value branch (critical path)
    wprep_kernel<<<(768*768 + 255)/256, 256, 0, s1>>>(vp_w, wv, 768, 768, 768);
    ln_kernel<<<MV/8, 256, 0, s1>>>(feat, fn_g, fn_b, nullptr, fnh);
    mma_gemm<<<dim3(6, MV/128), 256, GEMM_SMEM, s1>>>(fnh, wv, vp_b, nullptr, nullptr, nullptr, vb, MV, 768, 768, 768);
    cudaEventRecord(ev, s1);

    // s2: all other weight preps
    wprep_merged_kernel<<<(256*768 + 255)/256, 256, 0, s2>>>(off_w, aw_w, wfa);
    biascat_kernel<<<1, 256, 0, s2>>>(off_b, aw_b, fab);
    wprep_kernel<<<(768*768 + 255)/256, 256, 0, s2>>>(op_w,  wo, 768, 768, 768);
    wprep_kernel<<<(256*768 + 255)/256, 256, 0, s2>>>(fc1_w, w1, 192, 256, 768);
    wprep_kernel<<<(768*192 + 255)/256, 256, 0, s2>>>(fc2_w, w2, 768, 768, 192);
    cudaEventRecord(ew, s2);

    // s0: query branch
    ln_kernel<<<MQ/8, 256>>>(query, qn_g, qn_b, qf, qh);
    cudaStreamWaitEvent(0, ew, 0);
    mma_gemm<<<dim3(2, MQ/128), 256, GEMM_SMEM>>>(qh, wfa, fab, nullptr, nullptr, fa, nullptr, MQ, NFA, NFA, 768);
    cudaStreamWaitEvent(0, ev, 0);
    sample_kernel<<<MQ/2, 384>>>(refp, fa, vb, sph);
    // op proj + residuals: x = query + q + samp@op_w + op_b
    mma_gemm<<<dim3(6, MQ/128), 256, GEMM_SMEM>>>(sph, wo, op_b, qf, query, x, nullptr, MQ, 768, 768, 768);
    // FFN
    ln_kernel<<<MQ/8, 256>>>(x, ffn_g, ffn_b, nullptr, xlh);
    mma_gemm<<<dim3(2, MQ/128), 256, GEMM_SMEM>>>(xlh, w1, fc1_b, nullptr, nullptr, y, nullptr, MQ, 192, 192, 768);
    dwconv_gelu_kernel<<<MQ, HID>>>(y, dw_w, dw_b, ygh);
    mma_gemm<<<dim3(6, MQ/128), 256, GEMM_SMEM>>>(ygh, w2, fc2_b, x, nullptr, (float*)d_out, nullptr, MQ, 768, 768, 192);
}

// round 8
// speedup vs baseline: 5.8399x; 1.1250x over previous
#include <cuda_runtime.h>
#include <cuda_fp16.h>
#include <math.h>
#include <stdint.h>

#define DIM    768
#define HEADS  6
#define HDIM   128
#define HID    192
#define BATCH  4
#define NQ     4096
#define NV     21504
#define MQ     (BATCH*NQ)     // 16384
#define MV     (BATCH*NV)     // 86016
#define NFA    216            // merged off(144)+aw(72) output cols

// ---------------- helpers ----------------------------------------------------
__device__ __forceinline__ uint32_t smem_u32(const void* p) {
    uint32_t a;
    asm("{ .reg .u64 t; cvta.to.shared.u64 t, %1; cvt.u32.u64 %0, t; }" : "=r"(a) : "l"(p));
    return a;
}
__device__ __forceinline__ void cp16(uint32_t s, const void* g) {
    asm volatile("cp.async.cg.shared.global [%0], [%1], 16;" :: "r"(s), "l"(g));
}
__device__ __forceinline__ void cp_commit() { asm volatile("cp.async.commit_group;"); }
__device__ __forceinline__ void cp_wait0()  { asm volatile("cp.async.wait_group 0;"); }
__device__ __forceinline__ void cp_wait1()  { asm volatile("cp.async.wait_group 1;"); }

__device__ __forceinline__ void ldm4(uint32_t* r, uint32_t a) {
    asm volatile("ldmatrix.sync.aligned.m8n8.x4.shared.b16 {%0,%1,%2,%3}, [%4];"
        : "=r"(r[0]), "=r"(r[1]), "=r"(r[2]), "=r"(r[3]) : "r"(a));
}
__device__ __forceinline__ void mma16816(float* c, const uint32_t* a, const uint32_t* b) {
    asm volatile("mma.sync.aligned.m16n8k16.row.col.f32.f16.f16.f32 "
        "{%0,%1,%2,%3}, {%4,%5,%6,%7}, {%8,%9}, {%0,%1,%2,%3};"
        : "+f"(c[0]), "+f"(c[1]), "+f"(c[2]), "+f"(c[3])
        : "r"(a[0]), "r"(a[1]), "r"(a[2]), "r"(a[3]), "r"(b[0]), "r"(b[1]));
}

// ---------------- scratch ----------------------------------------------------
__device__ __align__(16) float  g_qf  [(size_t)MQ*DIM];
__device__ __align__(16) __half g_qh  [(size_t)MQ*DIM];
__device__ __align__(16) __half g_fnh [(size_t)MV*DIM];
__device__ __align__(16) __half g_vb  [(size_t)MV*DIM];   // PERMUTED: [b][h][pos][128]
__device__ __align__(16) float  g_fa  [(size_t)MQ*NFA];
__device__ __align__(16) float  g_fab [256];
__device__ __align__(16) __half g_sph [(size_t)MQ*DIM];
__device__ __align__(16) float  g_x   [(size_t)MQ*DIM];
__device__ __align__(16) __half g_xlh [(size_t)MQ*DIM];
__device__ __align__(16) float  g_y   [(size_t)MQ*HID];
__device__ __align__(16) __half g_ygh [(size_t)MQ*HID];
__device__ __align__(16) __half g_wv [768*768];
__device__ __align__(16) __half g_wo [768*768];
__device__ __align__(16) __half g_wfa[256*768];
__device__ __align__(16) __half g_w1 [256*768];
__device__ __align__(16) __half g_w2 [768*192];

// ---------------- weight transpose: W[K,N] -> T[Npad,K] fp16 -----------------
__global__ __launch_bounds__(256)
void wprep_kernel(const float* __restrict__ W, __half* __restrict__ T,
                  int N, int Npad, int K)
{
    int idx = blockIdx.x * 256 + threadIdx.x;
    if (idx >= Npad * K) return;
    int n = idx / K, k = idx - n * K;
    float v = (n < N) ? W[(size_t)k * N + n] : 0.f;
    T[idx] = __float2half(v);
}

__global__ __launch_bounds__(256)
void wprep_merged_kernel(const float* __restrict__ Woff, const float* __restrict__ Waw,
                         __half* __restrict__ T)
{
    int idx = blockIdx.x * 256 + threadIdx.x;
    if (idx >= 256 * 768) return;
    int n = idx / 768, k = idx - n * 768;
    float v = 0.f;
    if (n < 144)      v = Woff[(size_t)k * 144 + n];
    else if (n < 216) v = Waw [(size_t)k * 72 + (n - 144)];
    T[idx] = __float2half(v);
}
__global__ void biascat_kernel(const float* __restrict__ ob, const float* __restrict__ ab,
                               float* __restrict__ out)
{
    int i = threadIdx.x;
    out[i] = (i < 144) ? ob[i] : (i < 216 ? ab[i - 144] : 0.f);
}

// ---------------- LayerNorm (768), warp-per-row, 512 threads -----------------
__global__ __launch_bounds__(512)
void ln_kernel(const float* __restrict__ in, const float* __restrict__ g,
               const float* __restrict__ b, float* __restrict__ outf,
               __half* __restrict__ outh)
{
    const int row  = blockIdx.x * 16 + (threadIdx.x >> 5);
    const int lane = threadIdx.x & 31;
    const float4* x4 = reinterpret_cast<const float4*>(in + (size_t)row * DIM);
    float4 v[6];
    float s = 0.f, ss = 0.f;
    #pragma unroll
    for (int j = 0; j < 6; j++) {
        v[j] = x4[lane + 32 * j];
        s  += v[j].x + v[j].y + v[j].z + v[j].w;
        ss += v[j].x * v[j].x + v[j].y * v[j].y + v[j].z * v[j].z + v[j].w * v[j].w;
    }
    #pragma unroll
    for (int o = 16; o > 0; o >>= 1) {
        s  += __shfl_xor_sync(0xffffffffu, s,  o);
        ss += __shfl_xor_sync(0xffffffffu, ss, o);
    }
    const float m = s * (1.f / DIM);
    const float r = rsqrtf(ss * (1.f / DIM) - m * m + 1e-6f);
    const float4* g4 = reinterpret_cast<const float4*>(g);
    const float4* b4 = reinterpret_cast<const float4*>(b);
    float4*       f4 = outf ? reinterpret_cast<float4*>(outf + (size_t)row * DIM) : nullptr;
    uint2*        h4 = reinterpret_cast<uint2*>(outh + (size_t)row * DIM);
    #pragma unroll
    for (int j = 0; j < 6; j++) {
        int i = lane + 32 * j;
        float4 gg = g4[i], bb = b4[i];
        float o0 = (v[j].x - m) * r * gg.x + bb.x;
        float o1 = (v[j].y - m) * r * gg.y + bb.y;
        float o2 = (v[j].z - m) * r * gg.z + bb.z;
        float o3 = (v[j].w - m) * r * gg.w + bb.w;
        if (f4) f4[i] = make_float4(o0, o1, o2, o3);
        __half2 p0 = __floats2half2_rn(o0, o1);
        __half2 p1 = __floats2half2_rn(o2, o3);
        uint2 u;
        u.x = *reinterpret_cast<uint32_t*>(&p0);
        u.y = *reinterpret_cast<uint32_t*>(&p1);
        h4[i] = u;
    }
}

// ---------------- fp16 mma.sync GEMM, 3-stage cp.async pipeline --------------
// If Cb != null, fp16 output is written PERMUTED for sampling:
//   Cb[((b*6 + col/128)*NV + pos)*128 + col%128], where b=row/NV, pos=row%NV.
__global__ __launch_bounds__(256, 2)
void mma_gemm(const __half* __restrict__ A, const __half* __restrict__ B,
              const float* __restrict__ bias, const float* __restrict__ add1,
              const float* __restrict__ add2, float* __restrict__ C,
              __half* __restrict__ Cb, int M, int N, int ldc, int K)
{
    extern __shared__ char smraw[];
    char* sm = (char*)(((uintptr_t)smraw + 1023) & ~(uintptr_t)1023);
    const uint32_t smBase = smem_u32(sm);

    const int tid  = threadIdx.x;
    const int lane = tid & 31, wid = tid >> 5;
    const int wm = (wid & 3) * 32;
    const int wn = (wid >> 2) * 64;
    const int m0 = blockIdx.y * 128, n0 = blockIdx.x * 128;

    const size_t strA = (size_t)K * 2;
    const char* gA = (const char*)A + (size_t)m0 * strA;
    const char* gB = (const char*)B + (size_t)n0 * strA;

    const int aRow = lane & 15;
    const int aCol = (lane >> 4) * 16;
    const int bRowOff = ((lane & 16) >> 1) + (lane & 7);
    const int bCol = (lane & 8) * 2;

    uint32_t aBase[2], aXor[2];
    #pragma unroll
    for (int mt = 0; mt < 2; mt++) {
        int row = wm + mt * 16 + aRow;
        aBase[mt] = (uint32_t)(row * 128);
        aXor[mt]  = (uint32_t)(aCol ^ ((row & 7) * 16));
    }
    uint32_t bBase[4], bXor[4];
    #pragma unroll
    for (int np = 0; np < 4; np++) {
        int row = wn + np * 16 + bRowOff;
        bBase[np] = (uint32_t)(16384 + row * 128);
        bXor[np]  = (uint32_t)(bCol ^ ((row & 7) * 16));
    }

    float acc[2][8][4];
    #pragma unroll
    for (int i = 0; i < 2; i++)
        #pragma unroll
        for (int j = 0; j < 8; j++)
            #pragma unroll
            for (int k = 0; k < 4; k++) acc[i][j][k] = 0.f;

    const int nCh = K >> 6;

    #define LOAD_CHUNK(kc_, st_) do {                                           \
        uint32_t dst = smBase + (uint32_t)(st_) * 32768u;                       \
        size_t kb_ = (size_t)(kc_) * 128;                                       \
        _Pragma("unroll")                                                       \
        for (int i_ = 0; i_ < 4; i_++) {                                        \
            int u_ = tid + 256 * i_;                                            \
            int r_ = u_ >> 3, c_ = u_ & 7;                                      \
            uint32_t off_ = (uint32_t)(r_ * 128 + c_ * 16);                     \
            uint32_t sw_ = off_ ^ ((off_ >> 3) & 0x70);                         \
            size_t go_ = (size_t)r_ * strA + kb_ + (size_t)c_ * 16;             \
            cp16(dst + sw_,         gA + go_);                                  \
            cp16(dst + 16384 + sw_, gB + go_);                                  \
        }                                                                       \
    } while (0)

    LOAD_CHUNK(0, 0);
    cp_commit();
    if (nCh > 1) { LOAD_CHUNK(1, 1); cp_commit(); }

    for (int kc = 0; kc < nCh; kc++) {
        if (kc + 1 < nCh) cp_wait1(); else cp_wait0();
        __syncthreads();
        if (kc + 2 < nCh) {
            int st2 = (kc + 2) % 3;
            LOAD_CHUNK(kc + 2, st2);
            cp_commit();
        }
        const uint32_t stBase = smBase + (uint32_t)(kc % 3) * 32768u;
        #pragma unroll
        for (int ks = 0; ks < 4; ks++) {
            const uint32_t kb = (uint32_t)(ks * 32);
            uint32_t ah[2][4], bb[8][2];
            #pragma unroll
            for (int mt = 0; mt < 2; mt++)
                ldm4(ah[mt], stBase + aBase[mt] + (kb ^ aXor[mt]));
            #pragma unroll
            for (int np = 0; np < 4; np++)
                ldm4(&bb[2 * np][0], stBase + bBase[np] + (kb ^ bXor[np]));
            #pragma unroll
            for (int mt = 0; mt < 2; mt++)
                #pragma unroll
                for (int nt = 0; nt < 8; nt++) mma16816(acc[mt][nt], ah[mt], bb[nt]);
        }
    }
    #undef LOAD_CHUNK

    // epilogue
    #pragma unroll
    for (int mt = 0; mt < 2; mt++) {
        #pragma unroll
        for (int nt = 0; nt < 8; nt++) {
            int row = m0 + wm + mt * 16 + (lane >> 2);
            int col = n0 + wn + nt * 8 + 2 * (lane & 3);
            if (col < N) {
                #pragma unroll
                for (int half_ = 0; half_ < 2; half_++) {
                    int rr = row + half_ * 8;
                    size_t i0 = (size_t)rr * ldc + col;
                    float v0 = acc[mt][nt][half_ * 2 + 0] + bias[col];
                    float v1 = acc[mt][nt][half_ * 2 + 1] + bias[col + 1];
                    if (add1) { v0 += add1[i0]; v1 += add1[i0 + 1]; }
                    if (add2) { v0 += add2[i0]; v1 += add2[i0 + 1]; }
                    if (C) { C[i0] = v0; C[i0 + 1] = v1; }
                    if (Cb) {
                        // permuted write for sampling layout [b][h][pos][128]
                        int bidx = rr / NV, pos = rr - bidx * NV;
                        int hh = col >> 7, ch = col & 127;
                        size_t pi = (((size_t)(bidx * 6 + hh)) * NV + pos) * 128 + ch;
                        Cb[pi] = __float2half(v0); Cb[pi + 1] = __float2half(v1);
                    }
                }
            }
        }
    }
}

// ---------------- deformable sampling: 2 queries/block, permuted v -----------
__global__ __launch_bounds__(384)
void sample_kernel(const float* __restrict__ refp, const float* __restrict__ fa,
                   const __half* __restrict__ v, __half* __restrict__ outh)
{
    const int slot = threadIdx.x / 192;
    const int sub  = threadIdx.x % 192;
    const int bq   = blockIdx.x * 2 + slot;
    const int b    = bq / NQ;
    __shared__ float s_fa[2][NFA], s_w[2][72], s_x[2][72], s_y[2][72], s_ref[2][6];
    for (int i = sub; i < NFA; i += 192) s_fa[slot][i] = fa[(size_t)bq * NFA + i];
    if (sub < 6) s_ref[slot][sub] = refp[(size_t)bq * 6 + sub];
    __syncthreads();

    const int Hl[3] = {128, 64, 32};
    const int Wl[3] = {128, 64, 32};
    const int st[3] = {0, 16384, 20480};

    if (sub < 6) {
        int h = sub;
        const float* wrow = &s_fa[slot][144 + h * 12];
        float mx = -1e30f;
        for (int i = 0; i < 12; i++) mx = fmaxf(mx, wrow[i]);
        float sum = 0.f;
        float e[12];
        for (int i = 0; i < 12; i++) { e[i] = expf(wrow[i] - mx); sum += e[i]; }
        float inv = 1.f / sum;
        for (int i = 0; i < 12; i++) s_w[slot][h * 12 + i] = e[i] * inv;
    }
    if (sub < 72) {
        int h = sub / 12, lp = sub % 12, l = lp >> 2, p = lp & 3;
        float ox = s_fa[slot][h * 24 + l * 8 + p * 2 + 0];
        float oy = s_fa[slot][h * 24 + l * 8 + p * 2 + 1];
        float lx = s_ref[slot][l * 2 + 0] + ox / (float)Wl[l];
        float ly = s_ref[slot][l * 2 + 1] + oy / (float)Hl[l];
        s_x[slot][sub] = lx * (float)Wl[l] - 0.5f;
        s_y[slot][sub] = ly * (float)Hl[l] - 0.5f;
    }
    __syncthreads();

    const int h  = sub >> 5;
    const int c4 = (sub & 31) * 4;
    float a0 = 0.f, a1 = 0.f, a2 = 0.f, a3 = 0.f;
    #pragma unroll
    for (int lp = 0; lp < 12; lp++) {
        const int l  = lp >> 2;
        const int W_ = Wl[l], H_ = Hl[l];
        float w  = s_w[slot][h * 12 + lp];
        float x  = s_x[slot][h * 12 + lp];
        float y  = s_y[slot][h * 12 + lp];
        float x0f = floorf(x), y0f = floorf(y);
        float wx = x - x0f, wy = y - y0f;
        int x0 = (int)x0f, y0 = (int)y0f;
        // permuted layout: [b][h][pos][128]
        const __half* base = v + (((size_t)(b * 6 + h)) * NV + st[l]) * 128 + c4;
        float w00 = w * (1.f - wx) * (1.f - wy);
        float w10 = w * wx * (1.f - wy);
        float w01 = w * (1.f - wx) * wy;
        float w11 = w * wx * wy;
        #pragma unroll
        for (int cr = 0; cr < 4; cr++) {
            int xi = x0 + (cr & 1), yi = y0 + (cr >> 1);
            float cw = (cr == 0) ? w00 : (cr == 1) ? w10 : (cr == 2) ? w01 : w11;
            if (xi >= 0 && xi < W_ && yi >= 0 && yi < H_ && cw != 0.f) {
                uint2 u = *reinterpret_cast<const uint2*>(base + (size_t)(yi * W_ + xi) * 128);
                float2 p0 = __half22float2(*reinterpret_cast<__half2*>(&u.x));
                float2 p1 = __half22float2(*reinterpret_cast<__half2*>(&u.y));
                a0 += cw * p0.x;
                a1 += cw * p0.y;
                a2 += cw * p1.x;
                a3 += cw * p1.y;
            }
        }
    }
    size_t o = (size_t)bq * DIM + h * HDIM + c4;
    __half2 q0 = __floats2half2_rn(a0, a1);
    __half2 q1 = __floats2half2_rn(a2, a3);
    uint2 u;
    u.x = *reinterpret_cast<uint32_t*>(&q0);
    u.y = *reinterpret_cast<uint32_t*>(&q1);
    *reinterpret_cast<uint2*>(outh + o) = u;
}

// ---------------- depthwise 3x3 + GELU, 4 vertical pixels/thread -------------
__global__ __launch_bounds__(HID)
void dwconv_gelu_kernel(const float* __restrict__ y, const float* __restrict__ w,
                        const float* __restrict__ bias, __half* __restrict__ outh)
{
    // grid: B * 16 * 64 blocks; block handles rows h0..h0+3 at column ww
    const int idx = blockIdx.x;
    const int b   = idx >> 10;
    const int rem = idx & 1023;
    const int h0  = (rem >> 6) * 4;
    const int ww  = rem & 63;
    const int c   = threadIdx.x;

    float wreg[9];
    #pragma unroll
    for (int t = 0; t < 9; t++) wreg[t] = w[t * HID + c];
    const float bs = bias[c];

    // load 6 rows x 3 cols (with bounds)
    float vin[6][3];
    #pragma unroll
    for (int rr = 0; rr < 6; rr++) {
        int hh = h0 + rr - 1;
        #pragma unroll
        for (int cc = 0; cc < 3; cc++) {
            int xx = ww + cc - 1;
            vin[rr][cc] = (hh >= 0 && hh < 64 && xx >= 0 && xx < 64)
                ? y[((size_t)(b * 4096 + hh * 64 + xx)) * HID + c] : 0.f;
        }
    }
    #pragma unroll
    for (int p = 0; p < 4; p++) {
        float acc = bs;
        #pragma unroll
        for (int ky = 0; ky < 3; ky++)
            #pragma unroll
            for (int kx = 0; kx < 3; kx++)
                acc += vin[p + ky][kx] * wreg[ky * 3 + kx];
        float g = 0.5f * acc * (1.f + erff(acc * 0.70710678118654752f));
        outh[((size_t)(b * 4096 + (h0 + p) * 64 + ww)) * HID + c] = __float2half(g);
    }
}

// ---------------- host orchestration ----------------------------------------
#define GEMM_SMEM (98304 + 1024)

extern "C" void kernel_launch(void* const* d_in, const int* in_sizes, int n_in,
                              void* d_out, int out_size)
{
    const float* query = (const float*)d_in[0];
    const float* refp  = (const float*)d_in[1];
    const float* feat  = (const float*)d_in[2];
    const int wb = n_in - 20;
    const float* qn_g  = (const float*)d_in[wb + 0];
    const float* qn_b  = (const float*)d_in[wb + 1];
    const float* fn_g  = (const float*)d_in[wb + 2];
    const float* fn_b  = (const float*)d_in[wb + 3];
    const float* off_w = (const float*)d_in[wb + 4];
    const float* off_b = (const float*)d_in[wb + 5];
    const float* aw_w  = (const float*)d_in[wb + 6];
    const float* aw_b  = (const float*)d_in[wb + 7];
    const float* vp_w  = (const float*)d_in[wb + 8];
    const float* vp_b  = (const float*)d_in[wb + 9];
    const float* op_w  = (const float*)d_in[wb + 10];
    const float* op_b  = (const float*)d_in[wb + 11];
    const float* ffn_g = (const float*)d_in[wb + 12];
    const float* ffn_b = (const float*)d_in[wb + 13];
    const float* fc1_w = (const float*)d_in[wb + 14];
    const float* fc1_b = (const float*)d_in[wb + 15];
    const float* dw_w  = (const float*)d_in[wb + 16];
    const float* dw_b  = (const float*)d_in[wb + 17];
    const float* fc2_w = (const float*)d_in[wb + 18];
    const float* fc2_b = (const float*)d_in[wb + 19];

    static cudaStream_t s1 = nullptr, s2 = nullptr;
    static cudaEvent_t e0, ev, ew;
    if (!s1) {
        cudaStreamCreateWithFlags(&s1, cudaStreamNonBlocking);
        cudaStreamCreateWithFlags(&s2, cudaStreamNonBlocking);
        cudaEventCreateWithFlags(&e0, cudaEventDisableTiming);
        cudaEventCreateWithFlags(&ev, cudaEventDisableTiming);
        cudaEventCreateWithFlags(&ew, cudaEventDisableTiming);
        cudaFuncSetAttribute(mma_gemm, cudaFuncAttributeMaxDynamicSharedMemorySize, GEMM_SMEM);
    }

    float *qf, *fa, *fab, *x, *y;
    __half *qh, *fnh, *vb, *sph, *xlh, *ygh;
    __half *wv, *wo, *wfa, *w1, *w2;
    cudaGetSymbolAddress((void**)&qf,  g_qf);  cudaGetSymbolAddress((void**)&qh,  g_qh);
    cudaGetSymbolAddress((void**)&fnh, g_fnh); cudaGetSymbolAddress((void**)&vb,  g_vb);
    cudaGetSymbolAddress((void**)&fa,  g_fa);  cudaGetSymbolAddress((void**)&fab, g_fab);
    cudaGetSymbolAddress((void**)&sph, g_sph); cudaGetSymbolAddress((void**)&x,   g_x);
    cudaGetSymbolAddress((void**)&xlh, g_xlh); cudaGetSymbolAddress((void**)&y,   g_y);
    cudaGetSymbolAddress((void**)&ygh, g_ygh);
    cudaGetSymbolAddress((void**)&wv,  g_wv);  cudaGetSymbolAddress((void**)&wo,  g_wo);
    cudaGetSymbolAddress((void**)&wfa, g_wfa); cudaGetSymbolAddress((void**)&w1,  g_w1);
    cudaGetSymbolAddress((void**)&w2,  g_w2);

    // fork
    cudaEventRecord(e0, 0);
    cudaStreamWaitEvent(s1, e0, 0);
    cudaStreamWaitEvent(s2, e0, 0);

    // enqueue order arranged so launch #5 = vp mma_gemm (ncu -s 5 -c 1)
    wprep_kernel<<<(768*768 + 255)/256, 256, 0, s1>>>(vp_w, wv, 768, 768, 768);   // 0
    ln_kernel<<<MV/16, 512, 0, s1>>>(feat, fn_g, fn_b, nullptr, fnh);             // 1
    wprep_merged_kernel<<<(256*768 + 255)/256, 256, 0, s2>>>(off_w, aw_w, wfa);   // 2
    biascat_kernel<<<1, 256, 0, s2>>>(off_b, aw_b, fab);                          // 3
    ln_kernel<<<MQ/16, 512>>>(query, qn_g, qn_b, qf, qh);                         // 4
    mma_gemm<<<dim3(6, MV/128), 256, GEMM_SMEM, s1>>>(fnh, wv, vp_b, nullptr, nullptr, nullptr, vb, MV, 768, 768, 768);  // 5
    cudaEventRecord(ev, s1);

    wprep_kernel<<<(768*768 + 255)/256, 256, 0, s2>>>(op_w,  wo, 768, 768, 768);
    wprep_kernel<<<(256*768 + 255)/256, 256, 0, s2>>>(fc1_w, w1, 192, 256, 768);
    wprep_kernel<<<(768*192 + 255)/256, 256, 0, s2>>>(fc2_w, w2, 768, 768, 192);
    cudaEventRecord(ew, s2);

    cudaStreamWaitEvent(0, ew, 0);
    mma_gemm<<<dim3(2, MQ/128), 256, GEMM_SMEM>>>(qh, wfa, fab, nullptr, nullptr, fa, nullptr, MQ, NFA, NFA, 768);
    cudaStreamWaitEvent(0, ev, 0);
    sample_kernel<<<MQ/2, 384>>>(refp, fa, vb, sph);
    mma_gemm<<<dim3(6, MQ/128), 256, GEMM_SMEM>>>(sph, wo, op_b, qf, query, x, nullptr, MQ, 768, 768, 768);
    ln_kernel<<<MQ/16, 512>>>(x, ffn_g, ffn_b, nullptr, xlh);
    mma_gemm<<<dim3(2, MQ/128), 256, GEMM_SMEM>>>(xlh, w1, fc1_b, nullptr, nullptr, y, nullptr, MQ, 192, 192, 768);
    dwconv_gelu_kernel<<<BATCH*16*64, HID>>>(y, dw_w, dw_b, ygh);
    mma_gemm<<<dim3(6, MQ/128), 256, GEMM_SMEM>>>(ygh, w2, fc2_b, x, nullptr, (float*)d_out, nullptr, MQ, 768, 768, 192);
}